// round 6
// baseline (speedup 1.0000x reference)
#include <cuda_runtime.h>
#include <mma.h>
#include <cstdint>
#include <cstddef>
#include <math.h>

using namespace nvcuda;

#define BB 128
#define TT 256
#define RR 130
#define HH 1024
#define H3 3072
#define ZZ2 256
#define CC 24
#define ZC 280
#define KIN 410

static constexpr size_t GI_SZ = (size_t)TT * BB * H3;

__device__ __align__(128) float g_gi_f[GI_SZ];
__device__ __align__(128) float g_gi_b[GI_SZ];
__device__ __align__(128) float g_gi_gx[GI_SZ];
__device__ __align__(128) float g_h1all[(size_t)TT * BB * HH];
__device__ __align__(128) float g_zpart[BB * H3];
__device__ __align__(128) float g_zfull[BB * ZC];
__device__ __align__(128) float g_hf[2][BB * HH];
__device__ __align__(128) float g_hb[2][BB * HH];
__device__ __align__(128) float g_h0[2][BB * HH];
__device__ __align__(128) float g_h1[2][BB * HH];

static constexpr size_t OFF_MU  = (size_t)BB * TT * RR;
static constexpr size_t OFF_STD = OFF_MU + (size_t)BB * ZZ2;
static constexpr size_t OFF_Z   = OFF_STD + (size_t)BB * ZZ2;

__device__ __forceinline__ float sigf(float v) { return 1.f / (1.f + expf(-v)); }

// ---------------------------------------------------------------------------
__global__ void k_init() {
    int i = blockIdx.x * blockDim.x + threadIdx.x;
    if (i < BB * HH) { g_hf[0][i] = 0.f; g_hb[0][i] = 0.f; }
}

// ---------------------------------------------------------------------------
// Input-side GEMMs for all timesteps: gi[t,b,:] = A(t,b) @ W^T + b_ih
// mode 0: A=x -> g_gi_f (w_ih_f); mode 1: A=x -> g_gi_b (w_ih_b)
// mode 2: A=dec_in (one-hot at t=0, x[t-1] after) -> g_gi_gx (w_ih_g[:, :130])
// ---------------------------------------------------------------------------
__global__ void __launch_bounds__(256) k_input_gemm(
    const float* __restrict__ x,
    const float* __restrict__ w_f, const float* __restrict__ bi_f,
    const float* __restrict__ w_b, const float* __restrict__ bi_b,
    const float* __restrict__ w_g, const float* __restrict__ bi_g)
{
    __shared__ __align__(16) float sm[8192];
    const int tid = threadIdx.x;
    const int warp = tid >> 5;
    const int wm = warp >> 1, wn = warp & 1;

    const int mode = blockIdx.z;
    const float* W  = (mode == 0) ? w_f : (mode == 1) ? w_b : w_g;
    const float* bi = (mode == 0) ? bi_f : (mode == 1) ? bi_b : bi_g;
    float* gout = (mode == 0) ? g_gi_f : (mode == 1) ? g_gi_b : g_gi_gx;
    const int wstride = (mode == 2) ? KIN : RR;

    const int m0 = blockIdx.y * 128;
    const int n0 = blockIdx.x * 64;
    float* sA = sm;        // 128 x 16 (stride 24)
    float* sB = sm + 3072; // 64 x 16 (stride 24)

    wmma::fragment<wmma::accumulator, 16, 16, 8, float> c[2][2];
#pragma unroll
    for (int s = 0; s < 2; s++)
#pragma unroll
        for (int s2 = 0; s2 < 2; s2++) wmma::fill_fragment(c[s][s2], 0.f);

    for (int kt = 0; kt < 9; ++kt) {
        const int k0 = kt * 16;
#pragma unroll
        for (int i = 0; i < 8; i++) {
            int e = tid + i * 256;
            int r = e >> 4, kk = e & 15;
            int m = m0 + r, k = k0 + kk;
            int tstep = m >> 7, b = m & 127;
            float v = 0.f;
            if (k < RR) {
                if (mode < 2) v = x[(size_t)b * TT * RR + (size_t)tstep * RR + k];
                else if (tstep == 0) v = (k == RR - 1) ? 1.f : 0.f;
                else v = x[(size_t)b * TT * RR + (size_t)(tstep - 1) * RR + k];
            }
            sA[r * 24 + kk] = v;
        }
#pragma unroll
        for (int i = 0; i < 4; i++) {
            int e = tid + i * 256;
            int col = e >> 4, kk = e & 15;
            int n = n0 + col, k = k0 + kk;
            sB[col * 24 + kk] = (k < RR) ? W[(size_t)n * wstride + k] : 0.f;
        }
        __syncthreads();
#pragma unroll
        for (int ks = 0; ks < 2; ks++) {
            wmma::fragment<wmma::matrix_a, 16, 16, 8, wmma::precision::tf32, wmma::row_major> a[2];
            wmma::fragment<wmma::matrix_b, 16, 16, 8, wmma::precision::tf32, wmma::col_major> bf[2];
#pragma unroll
            for (int s = 0; s < 2; s++) {
                wmma::load_matrix_sync(a[s], sA + (wm * 32 + s * 16) * 24 + ks * 8, 24);
#pragma unroll
                for (int i = 0; i < a[s].num_elements; i++) a[s].x[i] = wmma::__float_to_tf32(a[s].x[i]);
            }
#pragma unroll
            for (int s2 = 0; s2 < 2; s2++) {
                wmma::load_matrix_sync(bf[s2], sB + (wn * 32 + s2 * 16) * 24 + ks * 8, 24);
#pragma unroll
                for (int i = 0; i < bf[s2].num_elements; i++) bf[s2].x[i] = wmma::__float_to_tf32(bf[s2].x[i]);
            }
#pragma unroll
            for (int s = 0; s < 2; s++)
#pragma unroll
                for (int s2 = 0; s2 < 2; s2++)
                    wmma::mma_sync(c[s][s2], a[s], bf[s2], c[s][s2]);
        }
        __syncthreads();
    }
#pragma unroll
    for (int s = 0; s < 2; s++)
#pragma unroll
        for (int s2 = 0; s2 < 2; s2++)
            wmma::store_matrix_sync(sm + (wm * 32 + s * 16) * 64 + (wn * 32 + s2 * 16),
                                    c[s][s2], 64, wmma::mem_row_major);
    __syncthreads();
#pragma unroll
    for (int i = 0; i < 8; i++) {
        int e = tid + i * 256;
        int r = e >> 4, c4 = (e & 15) << 2;
        int n = n0 + c4;
        float4 v = *(float4*)(sm + r * 64 + c4);
        v.x += bi[n]; v.y += bi[n + 1]; v.z += bi[n + 2]; v.w += bi[n + 3];
        *(float4*)(gout + (size_t)(m0 + r) * H3 + n) = v;
    }
}

// ---------------------------------------------------------------------------
// One GRU step for 16 h-columns (all 128 batch rows). gh = h_old @ W^T + bhh,
// gates fused. gi1(+gi2) hold input-side preactivations (bias included in gi1).
// sm >= 7040 floats.
// ---------------------------------------------------------------------------
__device__ void gru_step_tile(
    const float* __restrict__ h_old, float* __restrict__ h_new,
    const float* __restrict__ W, const float* __restrict__ bhh,
    const float* __restrict__ gi1, const float* __restrict__ gi2,
    int ctile, float* sm)
{
    const int tid = threadIdx.x;
    const int warp = tid >> 5;
    float* sH = sm;        // 128 x 32 (stride 40)
    float* sW = sm + 5120; // 48 x 32 (stride 40)

    wmma::fragment<wmma::accumulator, 16, 16, 8, float> c[3];
#pragma unroll
    for (int q = 0; q < 3; q++) wmma::fill_fragment(c[q], 0.f);

    for (int kt = 0; kt < 32; ++kt) {
        const int k0 = kt * 32;
#pragma unroll
        for (int i = 0; i < 4; i++) {
            int e = tid + i * 256;
            int row = e >> 3, kk = (e & 7) << 2;
            *(float4*)(sH + row * 40 + kk) = *(const float4*)(h_old + (size_t)row * HH + k0 + kk);
        }
#pragma unroll
        for (int i = 0; i < 2; i++) {
            int e = tid + i * 256;
            if (e < 384) {
                int col = e >> 3, kk = (e & 7) << 2;
                int q = col >> 4, jl = col & 15;
                int g = q * HH + ctile * 16 + jl;
                *(float4*)(sW + col * 40 + kk) = *(const float4*)(W + (size_t)g * HH + k0 + kk);
            }
        }
        __syncthreads();
#pragma unroll
        for (int ks = 0; ks < 4; ks++) {
            wmma::fragment<wmma::matrix_a, 16, 16, 8, wmma::precision::tf32, wmma::row_major> a;
            wmma::load_matrix_sync(a, sH + warp * 16 * 40 + ks * 8, 40);
#pragma unroll
            for (int i = 0; i < a.num_elements; i++) a.x[i] = wmma::__float_to_tf32(a.x[i]);
#pragma unroll
            for (int q = 0; q < 3; q++) {
                wmma::fragment<wmma::matrix_b, 16, 16, 8, wmma::precision::tf32, wmma::col_major> bf;
                wmma::load_matrix_sync(bf, sW + q * 16 * 40 + ks * 8, 40);
#pragma unroll
                for (int i = 0; i < bf.num_elements; i++) bf.x[i] = wmma::__float_to_tf32(bf.x[i]);
                wmma::mma_sync(c[q], a, bf, c[q]);
            }
        }
        __syncthreads();
    }
    float* sG = sm; // 128 x 48
#pragma unroll
    for (int q = 0; q < 3; q++)
        wmma::store_matrix_sync(sG + warp * 16 * 48 + q * 16, c[q], 48, wmma::mem_row_major);
    __syncthreads();
#pragma unroll
    for (int i = 0; i < 8; i++) {
        int e = tid + i * 256;
        int row = e >> 4, jl = e & 15;
        int j = ctile * 16 + jl;
        const float* gr1 = gi1 + (size_t)row * H3;
        float ir = gr1[j], iz = gr1[HH + j], in_ = gr1[2 * HH + j];
        if (gi2) {
            const float* gr2 = gi2 + (size_t)row * H3;
            ir += gr2[j]; iz += gr2[HH + j]; in_ += gr2[2 * HH + j];
        }
        float hr = sG[row * 48 + jl]      + bhh[j];
        float hz = sG[row * 48 + 16 + jl] + bhh[HH + j];
        float hn = sG[row * 48 + 32 + jl] + bhh[2 * HH + j];
        float r = sigf(ir + hr);
        float u = sigf(iz + hz);
        float n = tanhf(in_ + r * hn);
        float ho = h_old[(size_t)row * HH + j];
        h_new[(size_t)row * HH + j] = (1.f - u) * n + u * ho;
    }
}

// ---------------------------------------------------------------------------
__global__ void __launch_bounds__(256) k_enc_step(int t, int p,
    const float* __restrict__ w_hh_f, const float* __restrict__ b_hh_f,
    const float* __restrict__ w_hh_b, const float* __restrict__ b_hh_b)
{
    __shared__ __align__(16) float sm[7040];
    if (blockIdx.y == 0)
        gru_step_tile(g_hf[p], g_hf[1 - p], w_hh_f, b_hh_f,
                      g_gi_f + (size_t)t * BB * H3, nullptr, blockIdx.x, sm);
    else
        gru_step_tile(g_hb[p], g_hb[1 - p], w_hh_b, b_hh_b,
                      g_gi_b + (size_t)(TT - 1 - t) * BB * H3, nullptr, blockIdx.x, sm);
}

__global__ void __launch_bounds__(256) k_dec1(int t, int p,
    const float* __restrict__ W, const float* __restrict__ bhh)
{
    __shared__ __align__(16) float sm[7040];
    gru_step_tile(g_h0[p], g_h0[1 - p], W, bhh,
                  g_gi_gx + (size_t)t * BB * H3, g_zpart, blockIdx.x, sm);
}

// ---------------------------------------------------------------------------
// Decoder cell 2: gi = h0n@Wi^T + bi, gh = h1p@Wh^T + bh, gates fused.
// ---------------------------------------------------------------------------
__global__ void __launch_bounds__(256) k_dec2(int t, int p,
    const float* __restrict__ Wi, const float* __restrict__ Wh,
    const float* __restrict__ bi, const float* __restrict__ bh)
{
    __shared__ __align__(16) float sm[7040];
    const float* h0n = g_h0[1 - p];
    const float* h1p = (t == 0) ? g_h0[1 - p] : g_h1[p];
    float* h1n = g_h1[1 - p];
    const int tid = threadIdx.x, warp = tid >> 5, ctile = blockIdx.x;
    float* sH = sm;
    float* sW = sm + 5120;

    wmma::fragment<wmma::accumulator, 16, 16, 8, float> c[2][3];
#pragma unroll
    for (int s = 0; s < 2; s++)
#pragma unroll
        for (int q = 0; q < 3; q++) wmma::fill_fragment(c[s][q], 0.f);

    for (int kt = 0; kt < 32; ++kt) {
        const int k0 = kt * 32;
#pragma unroll
        for (int src = 0; src < 2; src++) {
            const float* hs = src ? h1p : h0n;
            const float* Ws = src ? Wh : Wi;
#pragma unroll
            for (int i = 0; i < 4; i++) {
                int e = tid + i * 256;
                int row = e >> 3, kk = (e & 7) << 2;
                *(float4*)(sH + row * 40 + kk) = *(const float4*)(hs + (size_t)row * HH + k0 + kk);
            }
#pragma unroll
            for (int i = 0; i < 2; i++) {
                int e = tid + i * 256;
                if (e < 384) {
                    int col = e >> 3, kk = (e & 7) << 2;
                    int q = col >> 4, jl = col & 15;
                    int g = q * HH + ctile * 16 + jl;
                    *(float4*)(sW + col * 40 + kk) = *(const float4*)(Ws + (size_t)g * HH + k0 + kk);
                }
            }
            __syncthreads();
#pragma unroll
            for (int ks = 0; ks < 4; ks++) {
                wmma::fragment<wmma::matrix_a, 16, 16, 8, wmma::precision::tf32, wmma::row_major> a;
                wmma::load_matrix_sync(a, sH + warp * 16 * 40 + ks * 8, 40);
#pragma unroll
                for (int i = 0; i < a.num_elements; i++) a.x[i] = wmma::__float_to_tf32(a.x[i]);
#pragma unroll
                for (int q = 0; q < 3; q++) {
                    wmma::fragment<wmma::matrix_b, 16, 16, 8, wmma::precision::tf32, wmma::col_major> bf;
                    wmma::load_matrix_sync(bf, sW + q * 16 * 40 + ks * 8, 40);
#pragma unroll
                    for (int i = 0; i < bf.num_elements; i++) bf.x[i] = wmma::__float_to_tf32(bf.x[i]);
                    wmma::mma_sync(c[src][q], a, bf, c[src][q]);
                }
            }
            __syncthreads();
        }
    }
    float* sG = sm; // 128 x 48
#pragma unroll
    for (int q = 0; q < 3; q++)
        wmma::store_matrix_sync(sG + warp * 16 * 48 + q * 16, c[0][q], 48, wmma::mem_row_major);
    __syncthreads();
    float vi[24];
#pragma unroll
    for (int i = 0; i < 8; i++) {
        int e = tid + i * 256;
        int row = e >> 4, jl = e & 15;
        vi[i * 3 + 0] = sG[row * 48 + jl];
        vi[i * 3 + 1] = sG[row * 48 + 16 + jl];
        vi[i * 3 + 2] = sG[row * 48 + 32 + jl];
    }
    __syncthreads();
#pragma unroll
    for (int q = 0; q < 3; q++)
        wmma::store_matrix_sync(sG + warp * 16 * 48 + q * 16, c[1][q], 48, wmma::mem_row_major);
    __syncthreads();
#pragma unroll
    for (int i = 0; i < 8; i++) {
        int e = tid + i * 256;
        int row = e >> 4, jl = e & 15;
        int j = ctile * 16 + jl;
        float ir = vi[i * 3 + 0] + bi[j];
        float iz = vi[i * 3 + 1] + bi[HH + j];
        float in_ = vi[i * 3 + 2] + bi[2 * HH + j];
        float hr = sG[row * 48 + jl]      + bh[j];
        float hz = sG[row * 48 + 16 + jl] + bh[HH + j];
        float hn = sG[row * 48 + 32 + jl] + bh[2 * HH + j];
        float r = sigf(ir + hr);
        float u = sigf(iz + hz);
        float n = tanhf(in_ + r * hn);
        float ho = h1p[(size_t)row * HH + j];
        float out = (1.f - u) * n + u * ho;
        h1n[(size_t)row * HH + j] = out;
        g_h1all[((size_t)t * BB + row) * HH + j] = out;
    }
}

// ---------------------------------------------------------------------------
// mu / std / z heads + writes to d_out tail; fills g_zfull (z ++ chroma).
// ---------------------------------------------------------------------------
__global__ void __launch_bounds__(256) k_head(
    const float* __restrict__ chroma, const float* __restrict__ eps,
    const float* __restrict__ w_mu, const float* __restrict__ b_mu,
    const float* __restrict__ w_var, const float* __restrict__ b_var,
    float* __restrict__ out)
{
    __shared__ float sh[2048];
    int b = blockIdx.x, tid = threadIdx.x;
    for (int i = tid; i < HH; i += 256) {
        sh[i] = g_hf[0][(size_t)b * HH + i];
        sh[HH + i] = g_hb[0][(size_t)b * HH + i];
    }
    __syncthreads();
    int j = tid;
    float accm = b_mu[j], accv = b_var[j];
    const float* wm = w_mu + (size_t)j * 2048;
    const float* wv = w_var + (size_t)j * 2048;
    for (int k = 0; k < 2048; k++) { accm += sh[k] * wm[k]; accv += sh[k] * wv[k]; }
    float std = expf(accv);
    float z = accm + std * eps[(size_t)b * ZZ2 + j];
    g_zfull[b * ZC + j] = z;
    out[OFF_MU + (size_t)b * ZZ2 + j] = accm;
    out[OFF_STD + (size_t)b * ZZ2 + j] = std;
    out[OFF_Z + (size_t)b * ZC + j] = z;
    if (j < CC) {
        float cv = chroma[b * CC + j];
        g_zfull[b * ZC + ZZ2 + j] = cv;
        out[OFF_Z + (size_t)b * ZC + ZZ2 + j] = cv;
    }
}

__global__ void __launch_bounds__(256) k_hx0(
    const float* __restrict__ w_init, const float* __restrict__ b_init)
{
    __shared__ float sz[ZC];
    int b = blockIdx.x, tid = threadIdx.x;
    for (int i = tid; i < ZC; i += 256) sz[i] = g_zfull[b * ZC + i];
    __syncthreads();
    for (int j = tid; j < HH; j += 256) {
        float acc = b_init[j];
        const float* w = w_init + (size_t)j * ZC;
        for (int k = 0; k < ZC; k++) acc += sz[k] * w[k];
        g_h0[0][(size_t)b * HH + j] = acc;
    }
}

__global__ void __launch_bounds__(256) k_zpart(const float* __restrict__ w_ih_g)
{
    __shared__ float sz[ZC];
    int b = blockIdx.x, tid = threadIdx.x;
    for (int i = tid; i < ZC; i += 256) sz[i] = g_zfull[b * ZC + i];
    __syncthreads();
    for (int j = tid; j < H3; j += 256) {
        float acc = 0.f;
        const float* w = w_ih_g + (size_t)j * KIN + RR;
        for (int k = 0; k < ZC; k++) acc += sz[k] * w[k];
        g_zpart[(size_t)b * H3 + j] = acc;
    }
}

// ---------------------------------------------------------------------------
// Final: logits = h1all @ w_out^T + b_out, then log_softmax per row.
// M = T*B rows, grid 256 blocks of 128 rows, N padded 130 -> 144.
// ---------------------------------------------------------------------------
__global__ void __launch_bounds__(256) k_logits(
    const float* __restrict__ w_out, const float* __restrict__ b_out,
    float* __restrict__ out)
{
    __shared__ __align__(16) float sm[10880];
    const int tid = threadIdx.x, warp = tid >> 5, lane = tid & 31;
    const int m0 = blockIdx.x * 128;
    float* sH = sm;        // 128 x 32 (stride 40)
    float* sW = sm + 5120; // 144 x 32 (stride 40)

    wmma::fragment<wmma::accumulator, 16, 16, 8, float> c[9];
#pragma unroll
    for (int q = 0; q < 9; q++) wmma::fill_fragment(c[q], 0.f);

    for (int kt = 0; kt < 32; ++kt) {
        const int k0 = kt * 32;
#pragma unroll
        for (int i = 0; i < 4; i++) {
            int e = tid + i * 256;
            int row = e >> 3, kk = (e & 7) << 2;
            *(float4*)(sH + row * 40 + kk) =
                *(const float4*)(g_h1all + (size_t)(m0 + row) * HH + k0 + kk);
        }
#pragma unroll
        for (int i = 0; i < 5; i++) {
            int e = tid + i * 256;
            if (e < 1152) {
                int col = e >> 3, kk = (e & 7) << 2;
                float4 v = make_float4(0.f, 0.f, 0.f, 0.f);
                if (col < RR) v = *(const float4*)(w_out + (size_t)col * HH + k0 + kk);
                *(float4*)(sW + col * 40 + kk) = v;
            }
        }
        __syncthreads();
#pragma unroll
        for (int ks = 0; ks < 4; ks++) {
            wmma::fragment<wmma::matrix_a, 16, 16, 8, wmma::precision::tf32, wmma::row_major> a;
            wmma::load_matrix_sync(a, sH + warp * 16 * 40 + ks * 8, 40);
#pragma unroll
            for (int i = 0; i < a.num_elements; i++) a.x[i] = wmma::__float_to_tf32(a.x[i]);
#pragma unroll
            for (int q = 0; q < 9; q++) {
                wmma::fragment<wmma::matrix_b, 16, 16, 8, wmma::precision::tf32, wmma::col_major> bf;
                wmma::load_matrix_sync(bf, sW + q * 16 * 40 + ks * 8, 40);
#pragma unroll
                for (int i = 0; i < bf.num_elements; i++) bf.x[i] = wmma::__float_to_tf32(bf.x[i]);
                wmma::mma_sync(c[q], a, bf, c[q]);
            }
        }
        __syncthreads();
    }
    // two half-tiles of 64 rows each to fit shared (64 x 144)
    float* sG = sm;
    for (int half = 0; half < 2; half++) {
        __syncthreads();
        if ((warp >> 2) == half) {
#pragma unroll
            for (int q = 0; q < 9; q++)
                wmma::store_matrix_sync(sG + (warp & 3) * 16 * 144 + q * 16, c[q], 144,
                                        wmma::mem_row_major);
        }
        __syncthreads();
        for (int rr = warp; rr < 64; rr += 8) {
            int m = m0 + half * 64 + rr;
            float mx = -1e30f;
            for (int j = lane; j < RR; j += 32) {
                float v = sG[rr * 144 + j] + b_out[j];
                mx = fmaxf(mx, v);
            }
#pragma unroll
            for (int off = 16; off > 0; off >>= 1)
                mx = fmaxf(mx, __shfl_xor_sync(0xffffffffu, mx, off));
            float s = 0.f;
            for (int j = lane; j < RR; j += 32)
                s += expf(sG[rr * 144 + j] + b_out[j] - mx);
#pragma unroll
            for (int off = 16; off > 0; off >>= 1)
                s += __shfl_xor_sync(0xffffffffu, s, off);
            float lse = mx + logf(s);
            int b = m & 127, t = m >> 7;
            float* orow = out + ((size_t)b * TT + t) * RR;
            for (int j = lane; j < RR; j += 32)
                orow[j] = sG[rr * 144 + j] + b_out[j] - lse;
        }
    }
}

// ---------------------------------------------------------------------------
extern "C" void kernel_launch(void* const* d_in, const int* in_sizes, int n_in,
                              void* d_out, int out_size) {
    (void)in_sizes; (void)n_in; (void)out_size;
    const float* x       = (const float*)d_in[0];
    const float* chroma  = (const float*)d_in[1];
    const float* eps     = (const float*)d_in[2];
    const float* w_ih_f  = (const float*)d_in[3];
    const float* w_hh_f  = (const float*)d_in[4];
    const float* b_ih_f  = (const float*)d_in[5];
    const float* b_hh_f  = (const float*)d_in[6];
    const float* w_ih_b  = (const float*)d_in[7];
    const float* w_hh_b  = (const float*)d_in[8];
    const float* b_ih_b  = (const float*)d_in[9];
    const float* b_hh_b  = (const float*)d_in[10];
    const float* w_mu    = (const float*)d_in[11];
    const float* b_mu    = (const float*)d_in[12];
    const float* w_var   = (const float*)d_in[13];
    const float* b_var   = (const float*)d_in[14];
    const float* w_init  = (const float*)d_in[15];
    const float* b_init  = (const float*)d_in[16];
    const float* w_ih_g  = (const float*)d_in[17];
    const float* w_hh_g  = (const float*)d_in[18];
    const float* b_ih_g  = (const float*)d_in[19];
    const float* b_hh_g  = (const float*)d_in[20];
    const float* w_ih_g2 = (const float*)d_in[21];
    const float* w_hh_g2 = (const float*)d_in[22];
    const float* b_ih_g2 = (const float*)d_in[23];
    const float* b_hh_g2 = (const float*)d_in[24];
    const float* w_out   = (const float*)d_in[25];
    const float* b_out   = (const float*)d_in[26];
    float* out = (float*)d_out;

    k_init<<<512, 256>>>();
    k_input_gemm<<<dim3(48, 256, 3), 256>>>(x, w_ih_f, b_ih_f, w_ih_b, b_ih_b,
                                            w_ih_g, b_ih_g);
    for (int t = 0; t < TT; t++)
        k_enc_step<<<dim3(64, 2), 256>>>(t, t & 1, w_hh_f, b_hh_f, w_hh_b, b_hh_b);
    k_head<<<BB, 256>>>(chroma, eps, w_mu, b_mu, w_var, b_var, out);
    k_hx0<<<BB, 256>>>(w_init, b_init);
    k_zpart<<<BB, 256>>>(w_ih_g);
    for (int t = 0; t < TT; t++) {
        int p = t & 1;
        k_dec1<<<64, 256>>>(t, p, w_hh_g, b_hh_g);
        k_dec2<<<64, 256>>>(t, p, w_ih_g2, w_hh_g2, b_ih_g2, b_hh_g2);
    }
    k_logits<<<256, 256>>>(w_out, b_out, out);
}

// round 7
// speedup vs baseline: 1.9461x; 1.9461x over previous
#include <cuda_runtime.h>
#include <mma.h>
#include <cstdint>
#include <cstddef>
#include <math.h>

using namespace nvcuda;

#define BB 128
#define TT 256
#define RR 130
#define HH 1024
#define H3 3072
#define ZZ2 256
#define CC 24
#define ZC 280
#define KIN 410

// persistent-kernel shared memory layout (floats)
#define WLD 1028                 // padded leading dim for resident W slice
#define SW_F (48 * WLD)          // 49344: resident W (48 gate cols x 1024 k)
#define SS_F 7040                // staging: sH(128x40)=5120 + sWs(48x40)=1920 ; sG(128x48)=6144 overlaps
#define SB_OFF (SW_F + SS_F)     // 56384: bias slice (96 floats)
#define SMEM_FLOATS (SB_OFF + 96)
#define SMEM_BYTES (SMEM_FLOATS * 4)

static constexpr size_t GI_SZ = (size_t)TT * BB * H3;

__device__ __align__(128) float g_gi_f[GI_SZ];
__device__ __align__(128) float g_gi_b[GI_SZ];
__device__ __align__(128) float g_gi_gx[GI_SZ];
__device__ __align__(128) float g_h1all[(size_t)TT * BB * HH];
__device__ __align__(128) float g_zpart[BB * H3];
__device__ __align__(128) float g_zfull[BB * ZC];
__device__ __align__(128) float g_hf[2][BB * HH];
__device__ __align__(128) float g_hb[2][BB * HH];
__device__ __align__(128) float g_h0[2][BB * HH];
__device__ __align__(128) float g_h1[2][BB * HH];

// software grid barriers (reset by k_init each invocation)
__device__ volatile int g_gen_e; __device__ unsigned int g_cnt_e;
__device__ volatile int g_gen_1; __device__ unsigned int g_cnt_1;
__device__ volatile int g_gen_2; __device__ unsigned int g_cnt_2;

static constexpr size_t OFF_MU  = (size_t)BB * TT * RR;
static constexpr size_t OFF_STD = OFF_MU + (size_t)BB * ZZ2;
static constexpr size_t OFF_Z   = OFF_STD + (size_t)BB * ZZ2;

__device__ __forceinline__ float sigf(float v) { return 1.f / (1.f + expf(-v)); }
#define TF32(x) wmma::__float_to_tf32(x)

// ---------------------------------------------------------------------------
__global__ void k_init() {
    int i = blockIdx.x * blockDim.x + threadIdx.x;
    if (i < BB * HH) { g_hf[0][i] = 0.f; g_hb[0][i] = 0.f; }
    if (i == 0) {
        g_gen_e = 0; g_cnt_e = 0;
        g_gen_1 = 0; g_cnt_1 = 0;
        g_gen_2 = 0; g_cnt_2 = 0;
    }
}

// generation barrier over nb co-resident blocks; target strictly increasing
__device__ __forceinline__ void group_barrier(unsigned int* cnt, volatile int* gen,
                                              int target, int nb) {
    __syncthreads();
    if (threadIdx.x == 0) {
        __threadfence();
        if (atomicAdd(cnt, 1u) == (unsigned)(nb - 1)) {
            atomicExch(cnt, 0u);
            __threadfence();
            *gen = target;
        } else {
            while (*gen < target) { }
            __threadfence();
        }
    }
    __syncthreads();
}

__device__ __forceinline__ void wait_gen(volatile int* gen, int target) {
    if (threadIdx.x == 0) {
        while (*gen < target) { }
        __threadfence();
    }
    __syncthreads();
}

// ---------------------------------------------------------------------------
// Input-side GEMMs for all timesteps (unchanged from R4): gi = A @ W^T + b_ih
// ---------------------------------------------------------------------------
__global__ void __launch_bounds__(256) k_input_gemm(
    const float* __restrict__ x,
    const float* __restrict__ w_f, const float* __restrict__ bi_f,
    const float* __restrict__ w_b, const float* __restrict__ bi_b,
    const float* __restrict__ w_g, const float* __restrict__ bi_g)
{
    __shared__ __align__(16) float sm[8192];
    const int tid = threadIdx.x;
    const int warp = tid >> 5;
    const int wm = warp >> 1, wn = warp & 1;

    const int mode = blockIdx.z;
    const float* W  = (mode == 0) ? w_f : (mode == 1) ? w_b : w_g;
    const float* bi = (mode == 0) ? bi_f : (mode == 1) ? bi_b : bi_g;
    float* gout = (mode == 0) ? g_gi_f : (mode == 1) ? g_gi_b : g_gi_gx;
    const int wstride = (mode == 2) ? KIN : RR;

    const int m0 = blockIdx.y * 128;
    const int n0 = blockIdx.x * 64;
    float* sA = sm;
    float* sB = sm + 3072;

    wmma::fragment<wmma::accumulator, 16, 16, 8, float> c[2][2];
#pragma unroll
    for (int s = 0; s < 2; s++)
#pragma unroll
        for (int s2 = 0; s2 < 2; s2++) wmma::fill_fragment(c[s][s2], 0.f);

    for (int kt = 0; kt < 9; ++kt) {
        const int k0 = kt * 16;
#pragma unroll
        for (int i = 0; i < 8; i++) {
            int e = tid + i * 256;
            int r = e >> 4, kk = e & 15;
            int m = m0 + r, k = k0 + kk;
            int tstep = m >> 7, b = m & 127;
            float v = 0.f;
            if (k < RR) {
                if (mode < 2) v = x[(size_t)b * TT * RR + (size_t)tstep * RR + k];
                else if (tstep == 0) v = (k == RR - 1) ? 1.f : 0.f;
                else v = x[(size_t)b * TT * RR + (size_t)(tstep - 1) * RR + k];
            }
            sA[r * 24 + kk] = v;
        }
#pragma unroll
        for (int i = 0; i < 4; i++) {
            int e = tid + i * 256;
            int col = e >> 4, kk = e & 15;
            int n = n0 + col, k = k0 + kk;
            sB[col * 24 + kk] = (k < RR) ? W[(size_t)n * wstride + k] : 0.f;
        }
        __syncthreads();
#pragma unroll
        for (int ks = 0; ks < 2; ks++) {
            wmma::fragment<wmma::matrix_a, 16, 16, 8, wmma::precision::tf32, wmma::row_major> a[2];
            wmma::fragment<wmma::matrix_b, 16, 16, 8, wmma::precision::tf32, wmma::col_major> bf[2];
#pragma unroll
            for (int s = 0; s < 2; s++) {
                wmma::load_matrix_sync(a[s], sA + (wm * 32 + s * 16) * 24 + ks * 8, 24);
#pragma unroll
                for (int i = 0; i < a[s].num_elements; i++) a[s].x[i] = TF32(a[s].x[i]);
            }
#pragma unroll
            for (int s2 = 0; s2 < 2; s2++) {
                wmma::load_matrix_sync(bf[s2], sB + (wn * 32 + s2 * 16) * 24 + ks * 8, 24);
#pragma unroll
                for (int i = 0; i < bf[s2].num_elements; i++) bf[s2].x[i] = TF32(bf[s2].x[i]);
            }
#pragma unroll
            for (int s = 0; s < 2; s++)
#pragma unroll
                for (int s2 = 0; s2 < 2; s2++)
                    wmma::mma_sync(c[s][s2], a[s], bf[s2], c[s][s2]);
        }
        __syncthreads();
    }
#pragma unroll
    for (int s = 0; s < 2; s++)
#pragma unroll
        for (int s2 = 0; s2 < 2; s2++)
            wmma::store_matrix_sync(sm + (wm * 32 + s * 16) * 64 + (wn * 32 + s2 * 16),
                                    c[s][s2], 64, wmma::mem_row_major);
    __syncthreads();
#pragma unroll
    for (int i = 0; i < 8; i++) {
        int e = tid + i * 256;
        int r = e >> 4, c4 = (e & 15) << 2;
        int n = n0 + c4;
        float4 v = *(float4*)(sm + r * 64 + c4);
        v.x += bi[n]; v.y += bi[n + 1]; v.z += bi[n + 2]; v.w += bi[n + 3];
        *(float4*)(gout + (size_t)(m0 + r) * H3 + n) = v;
    }
}

// ---------------------------------------------------------------------------
// Load a 48-row W slice (rows q*HH + ctile*16 + jl) into resident SMEM,
// tf32-rounded, layout [col][k] with leading dim WLD.
// ---------------------------------------------------------------------------
__device__ __forceinline__ void load_w_resident(const float* __restrict__ W,
                                                float* __restrict__ sW, int ctile) {
    const int tid = threadIdx.x;
#pragma unroll 4
    for (int i = 0; i < 48; i++) {
        int e = tid + (i << 8);
        int col = e >> 8, k4 = (e & 255) << 2;
        int q = col >> 4, jl = col & 15;
        float4 v = *(const float4*)(W + (size_t)(q * HH + ctile * 16 + jl) * HH + k4);
        v.x = TF32(v.x); v.y = TF32(v.y); v.z = TF32(v.z); v.w = TF32(v.w);
        *(float4*)(sW + col * WLD + k4) = v;
    }
}

// ---------------------------------------------------------------------------
// One GRU step with resident W: gh = h_old @ Wslice^T (+bias in sB[0..47]),
// fused gates. h loads bypass L1 (__ldcg). Register-prefetched k-pipeline.
// ---------------------------------------------------------------------------
__device__ __forceinline__ void gru_step_resident(
    const float* __restrict__ h_old, float* __restrict__ h_new,
    const float* __restrict__ sW, const float* __restrict__ sB,
    const float* __restrict__ gi1, const float* __restrict__ gi2,
    int ctile, float* sS)
{
    const int tid = threadIdx.x, warp = tid >> 5;
    float* sH = sS;

    wmma::fragment<wmma::accumulator, 16, 16, 8, float> c[3];
#pragma unroll
    for (int q = 0; q < 3; q++) wmma::fill_fragment(c[q], 0.f);

    int rowA[4], kkA[4];
#pragma unroll
    for (int i = 0; i < 4; i++) { int e = tid + (i << 8); rowA[i] = e >> 3; kkA[i] = (e & 7) << 2; }

    float4 rH[4];
#pragma unroll
    for (int i = 0; i < 4; i++)
        rH[i] = __ldcg((const float4*)(h_old + (size_t)rowA[i] * HH + kkA[i]));

    for (int kt = 0; kt < 32; kt++) {
#pragma unroll
        for (int i = 0; i < 4; i++) {
            float4 v = rH[i];
            v.x = TF32(v.x); v.y = TF32(v.y); v.z = TF32(v.z); v.w = TF32(v.w);
            *(float4*)(sH + rowA[i] * 40 + kkA[i]) = v;
        }
        __syncthreads();
        if (kt < 31) {
            const int k0 = (kt + 1) * 32;
#pragma unroll
            for (int i = 0; i < 4; i++)
                rH[i] = __ldcg((const float4*)(h_old + (size_t)rowA[i] * HH + k0 + kkA[i]));
        }
#pragma unroll
        for (int ks = 0; ks < 4; ks++) {
            wmma::fragment<wmma::matrix_a, 16, 16, 8, wmma::precision::tf32, wmma::row_major> a;
            wmma::load_matrix_sync(a, sH + warp * 16 * 40 + ks * 8, 40);
#pragma unroll
            for (int q = 0; q < 3; q++) {
                wmma::fragment<wmma::matrix_b, 16, 16, 8, wmma::precision::tf32, wmma::col_major> bf;
                wmma::load_matrix_sync(bf, sW + (q * 16) * WLD + kt * 32 + ks * 8, WLD);
                wmma::mma_sync(c[q], a, bf, c[q]);
            }
        }
        __syncthreads();
    }
    float* sG = sS; // 128 x 48
#pragma unroll
    for (int q = 0; q < 3; q++)
        wmma::store_matrix_sync(sG + warp * 16 * 48 + q * 16, c[q], 48, wmma::mem_row_major);
    __syncthreads();
#pragma unroll
    for (int i = 0; i < 8; i++) {
        int e = tid + (i << 8);
        int row = e >> 4, jl = e & 15;
        int j = ctile * 16 + jl;
        const float* gr1 = gi1 + (size_t)row * H3;
        float ir = gr1[j], iz = gr1[HH + j], in_ = gr1[2 * HH + j];
        if (gi2) {
            const float* gr2 = gi2 + (size_t)row * H3;
            ir += gr2[j]; iz += gr2[HH + j]; in_ += gr2[2 * HH + j];
        }
        float hr = sG[row * 48 + jl]      + sB[jl];
        float hz = sG[row * 48 + 16 + jl] + sB[16 + jl];
        float hn = sG[row * 48 + 32 + jl] + sB[32 + jl];
        float r = sigf(ir + hr);
        float u = sigf(iz + hz);
        float n = tanhf(in_ + r * hn);
        float ho = __ldcg(h_old + (size_t)row * HH + j);
        h_new[(size_t)row * HH + j] = (1.f - u) * n + u * ho;
    }
}

// ---------------------------------------------------------------------------
// Persistent encoder: 128 blocks (64 fwd + 64 bwd), 256 steps, grid barrier.
// ---------------------------------------------------------------------------
__global__ void __launch_bounds__(256) k_enc_persist(
    const float* __restrict__ w_hh_f, const float* __restrict__ b_hh_f,
    const float* __restrict__ w_hh_b, const float* __restrict__ b_hh_b)
{
    extern __shared__ __align__(16) float sm[];
    float* sW = sm;
    float* sS = sm + SW_F;
    float* sB = sm + SB_OFF;
    const int tid = threadIdx.x;
    const int dir = blockIdx.x >> 6, ctile = blockIdx.x & 63;
    const float* W   = dir ? w_hh_b : w_hh_f;
    const float* bhh = dir ? b_hh_b : b_hh_f;

    load_w_resident(W, sW, ctile);
    if (tid < 48) {
        int q = tid >> 4, jl = tid & 15;
        sB[tid] = bhh[q * HH + ctile * 16 + jl];
    }
    // first __syncthreads inside gru_step_resident covers sW/sB visibility

    for (int t = 0; t < TT; t++) {
        const int p = t & 1;
        const float* h_old = dir ? g_hb[p] : g_hf[p];
        float* h_new = dir ? g_hb[1 - p] : g_hf[1 - p];
        const float* gi = dir ? g_gi_b + (size_t)(TT - 1 - t) * BB * H3
                              : g_gi_f + (size_t)t * BB * H3;
        gru_step_resident(h_old, h_new, sW, sB, gi, nullptr, ctile, sS);
        group_barrier(&g_cnt_e, &g_gen_e, t + 1, 128);
    }
}

// ---------------------------------------------------------------------------
// Decoder cell2 step: ci = h0n @ Wi^T (Wi streamed), ch = h1p @ Wh^T (resident)
// ---------------------------------------------------------------------------
__device__ __forceinline__ void dec2_step(
    const float* __restrict__ h0n, const float* __restrict__ h1p,
    float* __restrict__ h1n, const float* __restrict__ Wi,
    const float* __restrict__ sWh, const float* __restrict__ sB,
    int ctile, float* sS, int t)
{
    const int tid = threadIdx.x, warp = tid >> 5;
    float* sH = sS;
    float* sWs = sS + 5120;

    wmma::fragment<wmma::accumulator, 16, 16, 8, float> ci[3], ch[3];
#pragma unroll
    for (int q = 0; q < 3; q++) { wmma::fill_fragment(ci[q], 0.f); wmma::fill_fragment(ch[q], 0.f); }

    int rowA[4], kkA[4];
#pragma unroll
    for (int i = 0; i < 4; i++) { int e = tid + (i << 8); rowA[i] = e >> 3; kkA[i] = (e & 7) << 2; }

    const float* wp[2]; int wst[2]; bool wact[2];
#pragma unroll
    for (int i = 0; i < 2; i++) {
        int e = tid + (i << 8);
        wact[i] = (e < 384);
        int col = e >> 3, kk = (e & 7) << 2;
        int g = (col >> 4) * HH + ctile * 16 + (col & 15);
        wp[i] = Wi + (size_t)g * HH + kk;
        wst[i] = col * 40 + kk;
    }

    // ---- phase 1: input side (stream Wi) ----
    float4 rH[4], rW[2];
#pragma unroll
    for (int i = 0; i < 4; i++)
        rH[i] = __ldcg((const float4*)(h0n + (size_t)rowA[i] * HH + kkA[i]));
#pragma unroll
    for (int i = 0; i < 2; i++) if (wact[i]) rW[i] = *(const float4*)(wp[i]);

    for (int kt = 0; kt < 32; kt++) {
#pragma unroll
        for (int i = 0; i < 4; i++) {
            float4 v = rH[i];
            v.x = TF32(v.x); v.y = TF32(v.y); v.z = TF32(v.z); v.w = TF32(v.w);
            *(float4*)(sH + rowA[i] * 40 + kkA[i]) = v;
        }
#pragma unroll
        for (int i = 0; i < 2; i++) if (wact[i]) {
            float4 v = rW[i];
            v.x = TF32(v.x); v.y = TF32(v.y); v.z = TF32(v.z); v.w = TF32(v.w);
            *(float4*)(sWs + wst[i]) = v;
        }
        __syncthreads();
        if (kt < 31) {
            const int k0 = (kt + 1) * 32;
#pragma unroll
            for (int i = 0; i < 4; i++)
                rH[i] = __ldcg((const float4*)(h0n + (size_t)rowA[i] * HH + k0 + kkA[i]));
#pragma unroll
            for (int i = 0; i < 2; i++) if (wact[i]) rW[i] = *(const float4*)(wp[i] + k0);
        }
#pragma unroll
        for (int ks = 0; ks < 4; ks++) {
            wmma::fragment<wmma::matrix_a, 16, 16, 8, wmma::precision::tf32, wmma::row_major> a;
            wmma::load_matrix_sync(a, sH + warp * 16 * 40 + ks * 8, 40);
#pragma unroll
            for (int q = 0; q < 3; q++) {
                wmma::fragment<wmma::matrix_b, 16, 16, 8, wmma::precision::tf32, wmma::col_major> bf;
                wmma::load_matrix_sync(bf, sWs + (q * 16) * 40 + ks * 8, 40);
                wmma::mma_sync(ci[q], a, bf, ci[q]);
            }
        }
        __syncthreads();
    }

    // ---- phase 2: hidden side (resident Wh) ----
#pragma unroll
    for (int i = 0; i < 4; i++)
        rH[i] = __ldcg((const float4*)(h1p + (size_t)rowA[i] * HH + kkA[i]));
    for (int kt = 0; kt < 32; kt++) {
#pragma unroll
        for (int i = 0; i < 4; i++) {
            float4 v = rH[i];
            v.x = TF32(v.x); v.y = TF32(v.y); v.z = TF32(v.z); v.w = TF32(v.w);
            *(float4*)(sH + rowA[i] * 40 + kkA[i]) = v;
        }
        __syncthreads();
        if (kt < 31) {
            const int k0 = (kt + 1) * 32;
#pragma unroll
            for (int i = 0; i < 4; i++)
                rH[i] = __ldcg((const float4*)(h1p + (size_t)rowA[i] * HH + k0 + kkA[i]));
        }
#pragma unroll
        for (int ks = 0; ks < 4; ks++) {
            wmma::fragment<wmma::matrix_a, 16, 16, 8, wmma::precision::tf32, wmma::row_major> a;
            wmma::load_matrix_sync(a, sH + warp * 16 * 40 + ks * 8, 40);
#pragma unroll
            for (int q = 0; q < 3; q++) {
                wmma::fragment<wmma::matrix_b, 16, 16, 8, wmma::precision::tf32, wmma::col_major> bf;
                wmma::load_matrix_sync(bf, sWh + (q * 16) * WLD + kt * 32 + ks * 8, WLD);
                wmma::mma_sync(ch[q], a, bf, ch[q]);
            }
        }
        __syncthreads();
    }

    // ---- epilogue (two accumulator spills through sG) ----
    float* sG = sS;
#pragma unroll
    for (int q = 0; q < 3; q++)
        wmma::store_matrix_sync(sG + warp * 16 * 48 + q * 16, ci[q], 48, wmma::mem_row_major);
    __syncthreads();
    float vi[24];
#pragma unroll
    for (int i = 0; i < 8; i++) {
        int e = tid + (i << 8);
        int row = e >> 4, jl = e & 15;
        vi[i * 3 + 0] = sG[row * 48 + jl];
        vi[i * 3 + 1] = sG[row * 48 + 16 + jl];
        vi[i * 3 + 2] = sG[row * 48 + 32 + jl];
    }
    __syncthreads();
#pragma unroll
    for (int q = 0; q < 3; q++)
        wmma::store_matrix_sync(sG + warp * 16 * 48 + q * 16, ch[q], 48, wmma::mem_row_major);
    __syncthreads();
#pragma unroll
    for (int i = 0; i < 8; i++) {
        int e = tid + (i << 8);
        int row = e >> 4, jl = e & 15;
        int j = ctile * 16 + jl;
        float ir  = vi[i * 3 + 0] + sB[jl];
        float iz  = vi[i * 3 + 1] + sB[16 + jl];
        float in_ = vi[i * 3 + 2] + sB[32 + jl];
        float hr = sG[row * 48 + jl]      + sB[48 + jl];
        float hz = sG[row * 48 + 16 + jl] + sB[64 + jl];
        float hn = sG[row * 48 + 32 + jl] + sB[80 + jl];
        float r = sigf(ir + hr);
        float u = sigf(iz + hz);
        float n = tanhf(in_ + r * hn);
        float ho = __ldcg(h1p + (size_t)row * HH + j);
        float o = (1.f - u) * n + u * ho;
        h1n[(size_t)row * HH + j] = o;
        g_h1all[((size_t)t * BB + row) * HH + j] = o;
    }
}

// ---------------------------------------------------------------------------
// Persistent decoder: blocks 0..63 = cell1 chain, 64..127 = cell2 chain,
// software-pipelined (cell2 lags cell1 by one step).
// ---------------------------------------------------------------------------
__global__ void __launch_bounds__(256) k_dec_persist(
    const float* __restrict__ w_hh_g,  const float* __restrict__ b_hh_g,
    const float* __restrict__ w_ih_g2, const float* __restrict__ w_hh_g2,
    const float* __restrict__ b_ih_g2, const float* __restrict__ b_hh_g2)
{
    extern __shared__ __align__(16) float sm[];
    float* sW = sm;
    float* sS = sm + SW_F;
    float* sB = sm + SB_OFF;
    const int tid = threadIdx.x;

    if (blockIdx.x < 64) {
        const int ctile = blockIdx.x;
        load_w_resident(w_hh_g, sW, ctile);
        if (tid < 48) {
            int q = tid >> 4, jl = tid & 15;
            sB[tid] = b_hh_g[q * HH + ctile * 16 + jl];
        }
        for (int t = 0; t < TT; t++) {
            if (t >= 2) wait_gen(&g_gen_2, t - 1);   // buffer reuse vs cell2 readers
            const int p = t & 1;
            gru_step_resident(g_h0[p], g_h0[1 - p], sW, sB,
                              g_gi_gx + (size_t)t * BB * H3, g_zpart, ctile, sS);
            group_barrier(&g_cnt_1, &g_gen_1, t + 1, 64);
        }
    } else {
        const int ctile = blockIdx.x - 64;
        load_w_resident(w_hh_g2, sW, ctile);
        if (tid < 48) {
            int q = tid >> 4, jl = tid & 15;
            sB[tid]      = b_ih_g2[q * HH + ctile * 16 + jl];
            sB[48 + tid] = b_hh_g2[q * HH + ctile * 16 + jl];
        }
        for (int t = 0; t < TT; t++) {
            wait_gen(&g_gen_1, t + 1);               // h0n(t) ready
            const int p = t & 1;
            const float* h0n = g_h0[1 - p];
            const float* h1p = (t == 0) ? g_h0[1] : g_h1[p];
            dec2_step(h0n, h1p, g_h1[1 - p], w_ih_g2, sW, sB, ctile, sS, t);
            group_barrier(&g_cnt_2, &g_gen_2, t + 1, 64);
        }
    }
}

// ---------------------------------------------------------------------------
// mu / std / z heads (unchanged)
// ---------------------------------------------------------------------------
__global__ void __launch_bounds__(256) k_head(
    const float* __restrict__ chroma, const float* __restrict__ eps,
    const float* __restrict__ w_mu, const float* __restrict__ b_mu,
    const float* __restrict__ w_var, const float* __restrict__ b_var,
    float* __restrict__ out)
{
    __shared__ float sh[2048];
    int b = blockIdx.x, tid = threadIdx.x;
    for (int i = tid; i < HH; i += 256) {
        sh[i] = g_hf[0][(size_t)b * HH + i];
        sh[HH + i] = g_hb[0][(size_t)b * HH + i];
    }
    __syncthreads();
    int j = tid;
    float accm = b_mu[j], accv = b_var[j];
    const float* wm = w_mu + (size_t)j * 2048;
    const float* wv = w_var + (size_t)j * 2048;
    for (int k = 0; k < 2048; k++) { accm += sh[k] * wm[k]; accv += sh[k] * wv[k]; }
    float std = expf(accv);
    float z = accm + std * eps[(size_t)b * ZZ2 + j];
    g_zfull[b * ZC + j] = z;
    out[OFF_MU + (size_t)b * ZZ2 + j] = accm;
    out[OFF_STD + (size_t)b * ZZ2 + j] = std;
    out[OFF_Z + (size_t)b * ZC + j] = z;
    if (j < CC) {
        float cv = chroma[b * CC + j];
        g_zfull[b * ZC + ZZ2 + j] = cv;
        out[OFF_Z + (size_t)b * ZC + ZZ2 + j] = cv;
    }
}

__global__ void __launch_bounds__(256) k_hx0(
    const float* __restrict__ w_init, const float* __restrict__ b_init)
{
    __shared__ float sz[ZC];
    int b = blockIdx.x, tid = threadIdx.x;
    for (int i = tid; i < ZC; i += 256) sz[i] = g_zfull[b * ZC + i];
    __syncthreads();
    for (int j = tid; j < HH; j += 256) {
        float acc = b_init[j];
        const float* w = w_init + (size_t)j * ZC;
        for (int k = 0; k < ZC; k++) acc += sz[k] * w[k];
        g_h0[0][(size_t)b * HH + j] = acc;
    }
}

__global__ void __launch_bounds__(256) k_zpart(const float* __restrict__ w_ih_g)
{
    __shared__ float sz[ZC];
    int b = blockIdx.x, tid = threadIdx.x;
    for (int i = tid; i < ZC; i += 256) sz[i] = g_zfull[b * ZC + i];
    __syncthreads();
    for (int j = tid; j < H3; j += 256) {
        float acc = 0.f;
        const float* w = w_ih_g + (size_t)j * KIN + RR;
        for (int k = 0; k < ZC; k++) acc += sz[k] * w[k];
        g_zpart[(size_t)b * H3 + j] = acc;
    }
}

// ---------------------------------------------------------------------------
// Final logits + log_softmax (unchanged)
// ---------------------------------------------------------------------------
__global__ void __launch_bounds__(256) k_logits(
    const float* __restrict__ w_out, const float* __restrict__ b_out,
    float* __restrict__ out)
{
    __shared__ __align__(16) float sm[10880];
    const int tid = threadIdx.x, warp = tid >> 5, lane = tid & 31;
    const int m0 = blockIdx.x * 128;
    float* sH = sm;
    float* sW = sm + 5120;

    wmma::fragment<wmma::accumulator, 16, 16, 8, float> c[9];
#pragma unroll
    for (int q = 0; q < 9; q++) wmma::fill_fragment(c[q], 0.f);

    for (int kt = 0; kt < 32; ++kt) {
        const int k0 = kt * 32;
#pragma unroll
        for (int i = 0; i < 4; i++) {
            int e = tid + i * 256;
            int row = e >> 3, kk = (e & 7) << 2;
            *(float4*)(sH + row * 40 + kk) =
                *(const float4*)(g_h1all + (size_t)(m0 + row) * HH + k0 + kk);
        }
#pragma unroll
        for (int i = 0; i < 5; i++) {
            int e = tid + i * 256;
            if (e < 1152) {
                int col = e >> 3, kk = (e & 7) << 2;
                float4 v = make_float4(0.f, 0.f, 0.f, 0.f);
                if (col < RR) v = *(const float4*)(w_out + (size_t)col * HH + k0 + kk);
                *(float4*)(sW + col * 40 + kk) = v;
            }
        }
        __syncthreads();
#pragma unroll
        for (int ks = 0; ks < 4; ks++) {
            wmma::fragment<wmma::matrix_a, 16, 16, 8, wmma::precision::tf32, wmma::row_major> a;
            wmma::load_matrix_sync(a, sH + warp * 16 * 40 + ks * 8, 40);
#pragma unroll
            for (int i = 0; i < a.num_elements; i++) a.x[i] = TF32(a.x[i]);
#pragma unroll
            for (int q = 0; q < 9; q++) {
                wmma::fragment<wmma::matrix_b, 16, 16, 8, wmma::precision::tf32, wmma::col_major> bf;
                wmma::load_matrix_sync(bf, sW + q * 16 * 40 + ks * 8, 40);
#pragma unroll
                for (int i = 0; i < bf.num_elements; i++) bf.x[i] = TF32(bf.x[i]);
                wmma::mma_sync(c[q], a, bf, c[q]);
            }
        }
        __syncthreads();
    }
    float* sG = sm;
    for (int half = 0; half < 2; half++) {
        __syncthreads();
        if ((warp >> 2) == half) {
#pragma unroll
            for (int q = 0; q < 9; q++)
                wmma::store_matrix_sync(sG + (warp & 3) * 16 * 144 + q * 16, c[q], 144,
                                        wmma::mem_row_major);
        }
        __syncthreads();
        for (int rr = warp; rr < 64; rr += 8) {
            int m = m0 + half * 64 + rr;
            float mx = -1e30f;
            for (int j = lane; j < RR; j += 32) {
                float v = sG[rr * 144 + j] + b_out[j];
                mx = fmaxf(mx, v);
            }
#pragma unroll
            for (int off = 16; off > 0; off >>= 1)
                mx = fmaxf(mx, __shfl_xor_sync(0xffffffffu, mx, off));
            float s = 0.f;
            for (int j = lane; j < RR; j += 32)
                s += expf(sG[rr * 144 + j] + b_out[j] - mx);
#pragma unroll
            for (int off = 16; off > 0; off >>= 1)
                s += __shfl_xor_sync(0xffffffffu, s, off);
            float lse = mx + logf(s);
            int b = m & 127, t = m >> 7;
            float* orow = out + ((size_t)b * TT + t) * RR;
            for (int j = lane; j < RR; j += 32)
                orow[j] = sG[rr * 144 + j] + b_out[j] - lse;
        }
    }
}

// ---------------------------------------------------------------------------
extern "C" void kernel_launch(void* const* d_in, const int* in_sizes, int n_in,
                              void* d_out, int out_size) {
    (void)in_sizes; (void)n_in; (void)out_size;
    const float* x       = (const float*)d_in[0];
    const float* chroma  = (const float*)d_in[1];
    const float* eps     = (const float*)d_in[2];
    const float* w_ih_f  = (const float*)d_in[3];
    const float* w_hh_f  = (const float*)d_in[4];
    const float* b_ih_f  = (const float*)d_in[5];
    const float* b_hh_f  = (const float*)d_in[6];
    const float* w_ih_b  = (const float*)d_in[7];
    const float* w_hh_b  = (const float*)d_in[8];
    const float* b_ih_b  = (const float*)d_in[9];
    const float* b_hh_b  = (const float*)d_in[10];
    const float* w_mu    = (const float*)d_in[11];
    const float* b_mu    = (const float*)d_in[12];
    const float* w_var   = (const float*)d_in[13];
    const float* b_var   = (const float*)d_in[14];
    const float* w_init  = (const float*)d_in[15];
    const float* b_init  = (const float*)d_in[16];
    const float* w_ih_g  = (const float*)d_in[17];
    const float* w_hh_g  = (const float*)d_in[18];
    const float* b_ih_g  = (const float*)d_in[19];
    const float* b_hh_g  = (const float*)d_in[20];
    const float* w_ih_g2 = (const float*)d_in[21];
    const float* w_hh_g2 = (const float*)d_in[22];
    const float* b_ih_g2 = (const float*)d_in[23];
    const float* b_hh_g2 = (const float*)d_in[24];
    const float* w_out   = (const float*)d_in[25];
    const float* b_out   = (const float*)d_in[26];
    float* out = (float*)d_out;

    cudaFuncSetAttribute(k_enc_persist, cudaFuncAttributeMaxDynamicSharedMemorySize, SMEM_BYTES);
    cudaFuncSetAttribute(k_dec_persist, cudaFuncAttributeMaxDynamicSharedMemorySize, SMEM_BYTES);

    k_init<<<512, 256>>>();
    k_input_gemm<<<dim3(48, 256, 3), 256>>>(x, w_ih_f, b_ih_f, w_ih_b, b_ih_b,
                                            w_ih_g, b_ih_g);
    k_enc_persist<<<128, 256, SMEM_BYTES>>>(w_hh_f, b_hh_f, w_hh_b, b_hh_b);
    k_head<<<BB, 256>>>(chroma, eps, w_mu, b_mu, w_var, b_var, out);
    k_hx0<<<BB, 256>>>(w_init, b_init);
    k_zpart<<<BB, 256>>>(w_ih_g);
    k_dec_persist<<<128, 256, SMEM_BYTES>>>(w_hh_g, b_hh_g, w_ih_g2, w_hh_g2,
                                            b_ih_g2, b_hh_g2);
    k_logits<<<256, 256>>>(w_out, b_out, out);
}

// round 11
// speedup vs baseline: 2.0581x; 1.0575x over previous
#include <cuda_runtime.h>
#include <mma.h>
#include <cstdint>
#include <cstddef>
#include <math.h>

using namespace nvcuda;

#define BB 128
#define TT 256
#define RR 130
#define HH 1024
#define H3 3072
#define ZZ2 256
#define CC 24
#define ZC 280
#define KIN 410

// persistent-kernel shared memory layout (floats)
#define WLD 1028                 // padded leading dim for resident W slice
#define SW_F (48 * WLD)          // 49344: resident W (48 gate cols x 1024 k)
#define SS_F 7040                // staging: sH(128x40)=5120 + sWs(48x40)=1920 ; sG(128x48)=6144 overlaps
#define SB_OFF (SW_F + SS_F)     // bias slice (96 floats)
#define SMEM_FLOATS (SB_OFF + 96)
#define SMEM_BYTES (SMEM_FLOATS * 4)

static constexpr size_t GI_SZ = (size_t)TT * BB * H3;

__device__ __align__(128) float g_gi_f[GI_SZ];
__device__ __align__(128) float g_gi_b[GI_SZ];
__device__ __align__(128) float g_gi_gx[GI_SZ];
__device__ __align__(128) float g_h1all[(size_t)TT * BB * HH];
__device__ __align__(128) float g_zpart[BB * H3];
__device__ __align__(128) float g_zfull[BB * ZC];
__device__ __align__(128) float g_hf[2][BB * HH];
__device__ __align__(128) float g_hb[2][BB * HH];
__device__ __align__(128) float g_h0[2][BB * HH];
__device__ __align__(128) float g_h1[2][BB * HH];

// software grid barriers (reset by k_init each invocation)
__device__ volatile int g_gen_ef; __device__ unsigned int g_cnt_ef;
__device__ volatile int g_gen_eb; __device__ unsigned int g_cnt_eb;
__device__ volatile int g_gen_1;  __device__ unsigned int g_cnt_1;
__device__ volatile int g_gen_2;  __device__ unsigned int g_cnt_2;

static constexpr size_t OFF_MU  = (size_t)BB * TT * RR;
static constexpr size_t OFF_STD = OFF_MU + (size_t)BB * ZZ2;
static constexpr size_t OFF_Z   = OFF_STD + (size_t)BB * ZZ2;

__device__ __forceinline__ float sigf(float v) { return 1.f / (1.f + expf(-v)); }
#define TF32(x) wmma::__float_to_tf32(x)

__device__ __forceinline__ float warp_sum(float v) {
#pragma unroll
    for (int off = 16; off > 0; off >>= 1)
        v += __shfl_xor_sync(0xffffffffu, v, off);
    return v;
}

// ---------------------------------------------------------------------------
__global__ void k_init() {
    int i = blockIdx.x * blockDim.x + threadIdx.x;
    if (i < BB * HH) { g_hf[0][i] = 0.f; g_hb[0][i] = 0.f; }
    if (i == 0) {
        g_gen_ef = 0; g_cnt_ef = 0;
        g_gen_eb = 0; g_cnt_eb = 0;
        g_gen_1 = 0;  g_cnt_1 = 0;
        g_gen_2 = 0;  g_cnt_2 = 0;
    }
}

// generation barrier over nb co-resident blocks; target strictly increasing
__device__ __forceinline__ void group_barrier(unsigned int* cnt, volatile int* gen,
                                              int target, int nb) {
    __syncthreads();
    if (threadIdx.x == 0) {
        __threadfence();
        if (atomicAdd(cnt, 1u) == (unsigned)(nb - 1)) {
            atomicExch(cnt, 0u);
            __threadfence();
            *gen = target;
        } else {
            while (*gen < target) { }
            __threadfence();
        }
    }
    __syncthreads();
}

__device__ __forceinline__ void wait_gen(volatile int* gen, int target) {
    if (threadIdx.x == 0) {
        while (*gen < target) { }
        __threadfence();
    }
    __syncthreads();
}

// ---------------------------------------------------------------------------
// Input-side GEMMs for all timesteps: gi = A @ W^T + b_ih
// ---------------------------------------------------------------------------
__global__ void __launch_bounds__(256) k_input_gemm(
    const float* __restrict__ x,
    const float* __restrict__ w_f, const float* __restrict__ bi_f,
    const float* __restrict__ w_b, const float* __restrict__ bi_b,
    const float* __restrict__ w_g, const float* __restrict__ bi_g)
{
    __shared__ __align__(16) float sm[8192];
    const int tid = threadIdx.x;
    const int warp = tid >> 5;
    const int wm = warp >> 1, wn = warp & 1;

    const int mode = blockIdx.z;
    const float* W  = (mode == 0) ? w_f : (mode == 1) ? w_b : w_g;
    const float* bi = (mode == 0) ? bi_f : (mode == 1) ? bi_b : bi_g;
    float* gout = (mode == 0) ? g_gi_f : (mode == 1) ? g_gi_b : g_gi_gx;
    const int wstride = (mode == 2) ? KIN : RR;

    const int m0 = blockIdx.y * 128;
    const int n0 = blockIdx.x * 64;
    float* sA = sm;
    float* sB = sm + 3072;

    wmma::fragment<wmma::accumulator, 16, 16, 8, float> c[2][2];
#pragma unroll
    for (int s = 0; s < 2; s++)
#pragma unroll
        for (int s2 = 0; s2 < 2; s2++) wmma::fill_fragment(c[s][s2], 0.f);

    for (int kt = 0; kt < 9; ++kt) {
        const int k0 = kt * 16;
#pragma unroll
        for (int i = 0; i < 8; i++) {
            int e = tid + i * 256;
            int r = e >> 4, kk = e & 15;
            int m = m0 + r, k = k0 + kk;
            int tstep = m >> 7, b = m & 127;
            float v = 0.f;
            if (k < RR) {
                if (mode < 2) v = x[(size_t)b * TT * RR + (size_t)tstep * RR + k];
                else if (tstep == 0) v = (k == RR - 1) ? 1.f : 0.f;
                else v = x[(size_t)b * TT * RR + (size_t)(tstep - 1) * RR + k];
            }
            sA[r * 24 + kk] = v;
        }
#pragma unroll
        for (int i = 0; i < 4; i++) {
            int e = tid + i * 256;
            int col = e >> 4, kk = e & 15;
            int n = n0 + col, k = k0 + kk;
            sB[col * 24 + kk] = (k < RR) ? W[(size_t)n * wstride + k] : 0.f;
        }
        __syncthreads();
#pragma unroll
        for (int ks = 0; ks < 2; ks++) {
            wmma::fragment<wmma::matrix_a, 16, 16, 8, wmma::precision::tf32, wmma::row_major> a[2];
            wmma::fragment<wmma::matrix_b, 16, 16, 8, wmma::precision::tf32, wmma::col_major> bf[2];
#pragma unroll
            for (int s = 0; s < 2; s++) {
                wmma::load_matrix_sync(a[s], sA + (wm * 32 + s * 16) * 24 + ks * 8, 24);
#pragma unroll
                for (int i = 0; i < a[s].num_elements; i++) a[s].x[i] = TF32(a[s].x[i]);
            }
#pragma unroll
            for (int s2 = 0; s2 < 2; s2++) {
                wmma::load_matrix_sync(bf[s2], sB + (wn * 32 + s2 * 16) * 24 + ks * 8, 24);
#pragma unroll
                for (int i = 0; i < bf[s2].num_elements; i++) bf[s2].x[i] = TF32(bf[s2].x[i]);
            }
#pragma unroll
            for (int s = 0; s < 2; s++)
#pragma unroll
                for (int s2 = 0; s2 < 2; s2++)
                    wmma::mma_sync(c[s][s2], a[s], bf[s2], c[s][s2]);
        }
        __syncthreads();
    }
#pragma unroll
    for (int s = 0; s < 2; s++)
#pragma unroll
        for (int s2 = 0; s2 < 2; s2++)
            wmma::store_matrix_sync(sm + (wm * 32 + s * 16) * 64 + (wn * 32 + s2 * 16),
                                    c[s][s2], 64, wmma::mem_row_major);
    __syncthreads();
#pragma unroll
    for (int i = 0; i < 8; i++) {
        int e = tid + i * 256;
        int r = e >> 4, c4 = (e & 15) << 2;
        int n = n0 + c4;
        float4 v = *(float4*)(sm + r * 64 + c4);
        v.x += bi[n]; v.y += bi[n + 1]; v.z += bi[n + 2]; v.w += bi[n + 3];
        *(float4*)(gout + (size_t)(m0 + r) * H3 + n) = v;
    }
}

// ---------------------------------------------------------------------------
// Load a 48-row W slice into resident SMEM, tf32-rounded, [col][k], ld WLD.
// ---------------------------------------------------------------------------
__device__ __forceinline__ void load_w_resident(const float* __restrict__ W,
                                                float* __restrict__ sW, int ctile) {
    const int tid = threadIdx.x;
#pragma unroll 4
    for (int i = 0; i < 48; i++) {
        int e = tid + (i << 8);
        int col = e >> 8, k4 = (e & 255) << 2;
        int q = col >> 4, jl = col & 15;
        float4 v = *(const float4*)(W + (size_t)(q * HH + ctile * 16 + jl) * HH + k4);
        v.x = TF32(v.x); v.y = TF32(v.y); v.z = TF32(v.z); v.w = TF32(v.w);
        *(float4*)(sW + col * WLD + k4) = v;
    }
}

// ---------------------------------------------------------------------------
// GRU step v2: warp tile 32 rows x 48 gate cols, 2-way split-K.
// Warps = 4 row-groups x 2 K-halves. sH stages 16 k of each half per chunk.
// Epilogue reduces the two K-half partials via sG in two rounds.
// ---------------------------------------------------------------------------
__device__ __forceinline__ void gru_step2(
    const float* __restrict__ h_old, float* __restrict__ h_new,
    const float* __restrict__ sW, const float* __restrict__ sB,
    const float* __restrict__ gi1, int ctile, float* sS)
{
    const int tid = threadIdx.x, warp = tid >> 5;
    const int mgrp = warp & 3, khalf = warp >> 2;
    float* sH = sS;

    // epilogue operand prefetch (ready at step start)
    float pgi[24], pho[8];
#pragma unroll
    for (int i = 0; i < 8; i++) {
        int e = tid + (i << 8);
        int row = e >> 4, jl = e & 15, j = ctile * 16 + jl;
        const float* gr = gi1 + (size_t)row * H3 + j;
        pgi[i * 3 + 0] = __ldg(gr);
        pgi[i * 3 + 1] = __ldg(gr + HH);
        pgi[i * 3 + 2] = __ldg(gr + 2 * HH);
        pho[i] = __ldcg(h_old + (size_t)row * HH + j);
    }

    wmma::fragment<wmma::accumulator, 16, 16, 8, float> c[2][3];
#pragma unroll
    for (int mt = 0; mt < 2; mt++)
#pragma unroll
        for (int q = 0; q < 3; q++) wmma::fill_fragment(c[mt][q], 0.f);

    int rowA[4], kkA[4], cbA[4];
#pragma unroll
    for (int i = 0; i < 4; i++) {
        int e = tid + (i << 8);
        rowA[i] = e >> 3;
        int kk = (e & 7) << 2;
        kkA[i] = kk;
        cbA[i] = (kk < 16) ? kk : 512 + kk - 16;   // half0 / half1 slab
    }

    float4 rH[4];
#pragma unroll
    for (int i = 0; i < 4; i++)
        rH[i] = __ldcg((const float4*)(h_old + (size_t)rowA[i] * HH + cbA[i]));

    for (int kt = 0; kt < 32; kt++) {
#pragma unroll
        for (int i = 0; i < 4; i++) {
            float4 v = rH[i];
            v.x = TF32(v.x); v.y = TF32(v.y); v.z = TF32(v.z); v.w = TF32(v.w);
            *(float4*)(sH + rowA[i] * 40 + kkA[i]) = v;
        }
        __syncthreads();
        if (kt < 31) {
            const int k0 = (kt + 1) * 16;
#pragma unroll
            for (int i = 0; i < 4; i++)
                rH[i] = __ldcg((const float4*)(h_old + (size_t)rowA[i] * HH + cbA[i] + k0));
        }
#pragma unroll
        for (int ks = 0; ks < 2; ks++) {
            wmma::fragment<wmma::matrix_a, 16, 16, 8, wmma::precision::tf32, wmma::row_major> a[2];
#pragma unroll
            for (int mt = 0; mt < 2; mt++)
                wmma::load_matrix_sync(a[mt], sH + (mgrp * 32 + mt * 16) * 40 + khalf * 16 + ks * 8, 40);
#pragma unroll
            for (int q = 0; q < 3; q++) {
                wmma::fragment<wmma::matrix_b, 16, 16, 8, wmma::precision::tf32, wmma::col_major> bf;
                wmma::load_matrix_sync(bf, sW + (q * 16) * WLD + khalf * 512 + kt * 16 + ks * 8, WLD);
#pragma unroll
                for (int mt = 0; mt < 2; mt++)
                    wmma::mma_sync(c[mt][q], a[mt], bf, c[mt][q]);
            }
        }
        __syncthreads();
    }

    // split-K reduce + gates
    float* sG = sS; // 128 x 48
    if (khalf == 0)
#pragma unroll
        for (int mt = 0; mt < 2; mt++)
#pragma unroll
            for (int q = 0; q < 3; q++)
                wmma::store_matrix_sync(sG + (mgrp * 32 + mt * 16) * 48 + q * 16,
                                        c[mt][q], 48, wmma::mem_row_major);
    __syncthreads();
    float vh[24];
#pragma unroll
    for (int i = 0; i < 8; i++) {
        int e = tid + (i << 8);
        int row = e >> 4, jl = e & 15;
        vh[i * 3 + 0] = sG[row * 48 + jl];
        vh[i * 3 + 1] = sG[row * 48 + 16 + jl];
        vh[i * 3 + 2] = sG[row * 48 + 32 + jl];
    }
    __syncthreads();
    if (khalf == 1)
#pragma unroll
        for (int mt = 0; mt < 2; mt++)
#pragma unroll
            for (int q = 0; q < 3; q++)
                wmma::store_matrix_sync(sG + (mgrp * 32 + mt * 16) * 48 + q * 16,
                                        c[mt][q], 48, wmma::mem_row_major);
    __syncthreads();
#pragma unroll
    for (int i = 0; i < 8; i++) {
        int e = tid + (i << 8);
        int row = e >> 4, jl = e & 15;
        int j = ctile * 16 + jl;
        float hr = vh[i * 3 + 0] + sG[row * 48 + jl]      + sB[jl];
        float hz = vh[i * 3 + 1] + sG[row * 48 + 16 + jl] + sB[16 + jl];
        float hn = vh[i * 3 + 2] + sG[row * 48 + 32 + jl] + sB[32 + jl];
        float r = sigf(pgi[i * 3 + 0] + hr);
        float u = sigf(pgi[i * 3 + 1] + hz);
        float n = tanhf(pgi[i * 3 + 2] + r * hn);
        h_new[(size_t)row * HH + j] = (1.f - u) * n + u * pho[i];
    }
}

// ---------------------------------------------------------------------------
// Persistent encoder: 64 blocks/direction, per-direction barriers.
// ---------------------------------------------------------------------------
__global__ void __launch_bounds__(256) k_enc_persist(
    const float* __restrict__ w_hh_f, const float* __restrict__ b_hh_f,
    const float* __restrict__ w_hh_b, const float* __restrict__ b_hh_b)
{
    extern __shared__ __align__(16) float sm[];
    float* sW = sm;
    float* sS = sm + SW_F;
    float* sB = sm + SB_OFF;
    const int tid = threadIdx.x;
    const int dir = blockIdx.x >> 6, ctile = blockIdx.x & 63;
    const float* W   = dir ? w_hh_b : w_hh_f;
    const float* bhh = dir ? b_hh_b : b_hh_f;
    unsigned int* cnt = dir ? &g_cnt_eb : &g_cnt_ef;
    volatile int* gen = dir ? &g_gen_eb : &g_gen_ef;

    load_w_resident(W, sW, ctile);
    if (tid < 48) {
        int q = tid >> 4, jl = tid & 15;
        sB[tid] = bhh[q * HH + ctile * 16 + jl];
    }
    // first __syncthreads inside gru_step2 covers sW/sB visibility

    for (int t = 0; t < TT; t++) {
        const int p = t & 1;
        const float* h_old = dir ? g_hb[p] : g_hf[p];
        float* h_new = dir ? g_hb[1 - p] : g_hf[1 - p];
        const float* gi = dir ? g_gi_b + (size_t)(TT - 1 - t) * BB * H3
                              : g_gi_f + (size_t)t * BB * H3;
        gru_step2(h_old, h_new, sW, sB, gi, ctile, sS);
        group_barrier(cnt, gen, t + 1, 64);
    }
}

// ---------------------------------------------------------------------------
// Decoder cell2 step v2: ci = h0n @ Wi^T (streamed), ch = h1p @ Wh^T (resident),
// both with 32x48 warp tiles and 2-way split-K; 4-round sG reduce.
// ---------------------------------------------------------------------------
__device__ __forceinline__ void dec2_step2(
    const float* __restrict__ h0n, const float* __restrict__ h1p,
    float* __restrict__ h1n, const float* __restrict__ Wi,
    const float* __restrict__ sWh, const float* __restrict__ sB,
    int ctile, float* sS, int t)
{
    const int tid = threadIdx.x, warp = tid >> 5;
    const int mgrp = warp & 3, khalf = warp >> 2;
    float* sH = sS;
    float* sWs = sS + 5120;

    float pho[8];
#pragma unroll
    for (int i = 0; i < 8; i++) {
        int e = tid + (i << 8);
        int row = e >> 4, jl = e & 15;
        pho[i] = __ldcg(h1p + (size_t)row * HH + ctile * 16 + jl);
    }

    wmma::fragment<wmma::accumulator, 16, 16, 8, float> ci[2][3], ch[2][3];
#pragma unroll
    for (int mt = 0; mt < 2; mt++)
#pragma unroll
        for (int q = 0; q < 3; q++) { wmma::fill_fragment(ci[mt][q], 0.f); wmma::fill_fragment(ch[mt][q], 0.f); }

    int rowA[4], kkA[4], cbA[4];
#pragma unroll
    for (int i = 0; i < 4; i++) {
        int e = tid + (i << 8);
        rowA[i] = e >> 3;
        int kk = (e & 7) << 2;
        kkA[i] = kk;
        cbA[i] = (kk < 16) ? kk : 512 + kk - 16;
    }
    const float* wp[2]; int wst[2]; bool wact[2];
#pragma unroll
    for (int i = 0; i < 2; i++) {
        int e = tid + (i << 8);
        wact[i] = (e < 384);
        int col = e >> 3, kk = (e & 7) << 2;
        int cb = (kk < 16) ? kk : 512 + kk - 16;
        int g = (col >> 4) * HH + ctile * 16 + (col & 15);
        wp[i] = Wi + (size_t)g * HH + cb;
        wst[i] = col * 40 + kk;
    }

    // ---- phase 1: input side (stream Wi, h0n) ----
    float4 rH[4], rW[2];
#pragma unroll
    for (int i = 0; i < 4; i++)
        rH[i] = __ldcg((const float4*)(h0n + (size_t)rowA[i] * HH + cbA[i]));
#pragma unroll
    for (int i = 0; i < 2; i++) if (wact[i]) rW[i] = __ldg((const float4*)(wp[i]));

    for (int kt = 0; kt < 32; kt++) {
#pragma unroll
        for (int i = 0; i < 4; i++) {
            float4 v = rH[i];
            v.x = TF32(v.x); v.y = TF32(v.y); v.z = TF32(v.z); v.w = TF32(v.w);
            *(float4*)(sH + rowA[i] * 40 + kkA[i]) = v;
        }
#pragma unroll
        for (int i = 0; i < 2; i++) if (wact[i]) {
            float4 v = rW[i];
            v.x = TF32(v.x); v.y = TF32(v.y); v.z = TF32(v.z); v.w = TF32(v.w);
            *(float4*)(sWs + wst[i]) = v;
        }
        __syncthreads();
        if (kt < 31) {
            const int k0 = (kt + 1) * 16;
#pragma unroll
            for (int i = 0; i < 4; i++)
                rH[i] = __ldcg((const float4*)(h0n + (size_t)rowA[i] * HH + cbA[i] + k0));
#pragma unroll
            for (int i = 0; i < 2; i++) if (wact[i]) rW[i] = __ldg((const float4*)(wp[i] + k0));
        }
#pragma unroll
        for (int ks = 0; ks < 2; ks++) {
            wmma::fragment<wmma::matrix_a, 16, 16, 8, wmma::precision::tf32, wmma::row_major> a[2];
#pragma unroll
            for (int mt = 0; mt < 2; mt++)
                wmma::load_matrix_sync(a[mt], sH + (mgrp * 32 + mt * 16) * 40 + khalf * 16 + ks * 8, 40);
#pragma unroll
            for (int q = 0; q < 3; q++) {
                wmma::fragment<wmma::matrix_b, 16, 16, 8, wmma::precision::tf32, wmma::col_major> bf;
                wmma::load_matrix_sync(bf, sWs + (q * 16) * 40 + khalf * 16 + ks * 8, 40);
#pragma unroll
                for (int mt = 0; mt < 2; mt++)
                    wmma::mma_sync(ci[mt][q], a[mt], bf, ci[mt][q]);
            }
        }
        __syncthreads();
    }

    // ---- phase 2: hidden side (resident Wh, h1p) ----
#pragma unroll
    for (int i = 0; i < 4; i++)
        rH[i] = __ldcg((const float4*)(h1p + (size_t)rowA[i] * HH + cbA[i]));
    for (int kt = 0; kt < 32; kt++) {
#pragma unroll
        for (int i = 0; i < 4; i++) {
            float4 v = rH[i];
            v.x = TF32(v.x); v.y = TF32(v.y); v.z = TF32(v.z); v.w = TF32(v.w);
            *(float4*)(sH + rowA[i] * 40 + kkA[i]) = v;
        }
        __syncthreads();
        if (kt < 31) {
            const int k0 = (kt + 1) * 16;
#pragma unroll
            for (int i = 0; i < 4; i++)
                rH[i] = __ldcg((const float4*)(h1p + (size_t)rowA[i] * HH + cbA[i] + k0));
        }
#pragma unroll
        for (int ks = 0; ks < 2; ks++) {
            wmma::fragment<wmma::matrix_a, 16, 16, 8, wmma::precision::tf32, wmma::row_major> a[2];
#pragma unroll
            for (int mt = 0; mt < 2; mt++)
                wmma::load_matrix_sync(a[mt], sH + (mgrp * 32 + mt * 16) * 40 + khalf * 16 + ks * 8, 40);
#pragma unroll
            for (int q = 0; q < 3; q++) {
                wmma::fragment<wmma::matrix_b, 16, 16, 8, wmma::precision::tf32, wmma::col_major> bf;
                wmma::load_matrix_sync(bf, sWh + (q * 16) * WLD + khalf * 512 + kt * 16 + ks * 8, WLD);
#pragma unroll
                for (int mt = 0; mt < 2; mt++)
                    wmma::mma_sync(ch[mt][q], a[mt], bf, ch[mt][q]);
            }
        }
        __syncthreads();
    }

    // ---- epilogue: 4-round split-K reduce through sG ----
    float* sG = sS;
    float vvi[24], vvh[24];
    // ci, khalf 0
    if (khalf == 0)
#pragma unroll
        for (int mt = 0; mt < 2; mt++)
#pragma unroll
            for (int q = 0; q < 3; q++)
                wmma::store_matrix_sync(sG + (mgrp * 32 + mt * 16) * 48 + q * 16, ci[mt][q], 48, wmma::mem_row_major);
    __syncthreads();
#pragma unroll
    for (int i = 0; i < 8; i++) {
        int e = tid + (i << 8); int row = e >> 4, jl = e & 15;
        vvi[i * 3 + 0] = sG[row * 48 + jl];
        vvi[i * 3 + 1] = sG[row * 48 + 16 + jl];
        vvi[i * 3 + 2] = sG[row * 48 + 32 + jl];
    }
    __syncthreads();
    // ci, khalf 1
    if (khalf == 1)
#pragma unroll
        for (int mt = 0; mt < 2; mt++)
#pragma unroll
            for (int q = 0; q < 3; q++)
                wmma::store_matrix_sync(sG + (mgrp * 32 + mt * 16) * 48 + q * 16, ci[mt][q], 48, wmma::mem_row_major);
    __syncthreads();
#pragma unroll
    for (int i = 0; i < 8; i++) {
        int e = tid + (i << 8); int row = e >> 4, jl = e & 15;
        vvi[i * 3 + 0] += sG[row * 48 + jl];
        vvi[i * 3 + 1] += sG[row * 48 + 16 + jl];
        vvi[i * 3 + 2] += sG[row * 48 + 32 + jl];
    }
    __syncthreads();
    // ch, khalf 0
    if (khalf == 0)
#pragma unroll
        for (int mt = 0; mt < 2; mt++)
#pragma unroll
            for (int q = 0; q < 3; q++)
                wmma::store_matrix_sync(sG + (mgrp * 32 + mt * 16) * 48 + q * 16, ch[mt][q], 48, wmma::mem_row_major);
    __syncthreads();
#pragma unroll
    for (int i = 0; i < 8; i++) {
        int e = tid + (i << 8); int row = e >> 4, jl = e & 15;
        vvh[i * 3 + 0] = sG[row * 48 + jl];
        vvh[i * 3 + 1] = sG[row * 48 + 16 + jl];
        vvh[i * 3 + 2] = sG[row * 48 + 32 + jl];
    }
    __syncthreads();
    // ch, khalf 1 + gates
    if (khalf == 1)
#pragma unroll
        for (int mt = 0; mt < 2; mt++)
#pragma unroll
            for (int q = 0; q < 3; q++)
                wmma::store_matrix_sync(sG + (mgrp * 32 + mt * 16) * 48 + q * 16, ch[mt][q], 48, wmma::mem_row_major);
    __syncthreads();
#pragma unroll
    for (int i = 0; i < 8; i++) {
        int e = tid + (i << 8);
        int row = e >> 4, jl = e & 15;
        int j = ctile * 16 + jl;
        float ir  = vvi[i * 3 + 0] + sB[jl];
        float iz  = vvi[i * 3 + 1] + sB[16 + jl];
        float in_ = vvi[i * 3 + 2] + sB[32 + jl];
        float hr = vvh[i * 3 + 0] + sG[row * 48 + jl]      + sB[48 + jl];
        float hz = vvh[i * 3 + 1] + sG[row * 48 + 16 + jl] + sB[64 + jl];
        float hn = vvh[i * 3 + 2] + sG[row * 48 + 32 + jl] + sB[80 + jl];
        float r = sigf(ir + hr);
        float u = sigf(iz + hz);
        float n = tanhf(in_ + r * hn);
        float o = (1.f - u) * n + u * pho[i];
        h1n[(size_t)row * HH + j] = o;
        g_h1all[((size_t)t * BB + row) * HH + j] = o;
    }
}

// ---------------------------------------------------------------------------
// Persistent decoder: blocks 0..63 = cell1 chain, 64..127 = cell2 chain.
// ---------------------------------------------------------------------------
__global__ void __launch_bounds__(256) k_dec_persist(
    const float* __restrict__ w_hh_g,  const float* __restrict__ b_hh_g,
    const float* __restrict__ w_ih_g2, const float* __restrict__ w_hh_g2,
    const float* __restrict__ b_ih_g2, const float* __restrict__ b_hh_g2)
{
    extern __shared__ __align__(16) float sm[];
    float* sW = sm;
    float* sS = sm + SW_F;
    float* sB = sm + SB_OFF;
    const int tid = threadIdx.x;

    if (blockIdx.x < 64) {
        const int ctile = blockIdx.x;
        load_w_resident(w_hh_g, sW, ctile);
        if (tid < 48) {
            int q = tid >> 4, jl = tid & 15;
            sB[tid] = b_hh_g[q * HH + ctile * 16 + jl];
        }
        for (int t = 0; t < TT; t++) {
            if (t >= 2) wait_gen(&g_gen_2, t - 1);   // buffer reuse vs cell2 readers
            const int p = t & 1;
            gru_step2(g_h0[p], g_h0[1 - p], sW, sB,
                      g_gi_gx + (size_t)t * BB * H3, ctile, sS);
            group_barrier(&g_cnt_1, &g_gen_1, t + 1, 64);
        }
    } else {
        const int ctile = blockIdx.x - 64;
        load_w_resident(w_hh_g2, sW, ctile);
        if (tid < 48) {
            int q = tid >> 4, jl = tid & 15;
            sB[tid]      = b_ih_g2[q * HH + ctile * 16 + jl];
            sB[48 + tid] = b_hh_g2[q * HH + ctile * 16 + jl];
        }
        for (int t = 0; t < TT; t++) {
            wait_gen(&g_gen_1, t + 1);               // h0n(t) ready
            const int p = t & 1;
            const float* h0n = g_h0[1 - p];
            const float* h1p = (t == 0) ? g_h0[1] : g_h1[p];
            dec2_step2(h0n, h1p, g_h1[1 - p], w_ih_g2, sW, sB, ctile, sS, t);
            group_barrier(&g_cnt_2, &g_gen_2, t + 1, 64);
        }
    }
}

// ---------------------------------------------------------------------------
// mu / std / z heads — warp-dot, coalesced weight reads.
// ---------------------------------------------------------------------------
__global__ void __launch_bounds__(256) k_head(
    const float* __restrict__ chroma, const float* __restrict__ eps,
    const float* __restrict__ w_mu, const float* __restrict__ b_mu,
    const float* __restrict__ w_var, const float* __restrict__ b_var,
    float* __restrict__ out)
{
    __shared__ float sh[2048];
    __shared__ float sacc[2 * ZZ2];
    int b = blockIdx.x, tid = threadIdx.x;
    int warp = tid >> 5, lane = tid & 31;
    for (int i = tid; i < HH; i += 256) {
        sh[i] = g_hf[0][(size_t)b * HH + i];
        sh[HH + i] = g_hb[0][(size_t)b * HH + i];
    }
    __syncthreads();
    for (int task = warp; task < 2 * ZZ2; task += 8) {
        int head = task >> 8, j = task & 255;
        const float* w = (head ? w_var : w_mu) + (size_t)j * 2048;
        float acc = 0.f;
        for (int k = lane; k < 2048; k += 32) acc += sh[k] * __ldg(w + k);
        acc = warp_sum(acc);
        if (lane == 0) sacc[task] = acc + (head ? b_var[j] : b_mu[j]);
    }
    __syncthreads();
    if (tid < ZZ2) {
        int j = tid;
        float accm = sacc[j];
        float std = expf(sacc[ZZ2 + j]);
        float z = accm + std * eps[(size_t)b * ZZ2 + j];
        g_zfull[b * ZC + j] = z;
        out[OFF_MU + (size_t)b * ZZ2 + j] = accm;
        out[OFF_STD + (size_t)b * ZZ2 + j] = std;
        out[OFF_Z + (size_t)b * ZC + j] = z;
        if (j < CC) {
            float cv = chroma[b * CC + j];
            g_zfull[b * ZC + ZZ2 + j] = cv;
            out[OFF_Z + (size_t)b * ZC + ZZ2 + j] = cv;
        }
    }
}

__global__ void __launch_bounds__(256) k_hx0(
    const float* __restrict__ w_init, const float* __restrict__ b_init)
{
    __shared__ float sz[ZC];
    int b = blockIdx.x, tid = threadIdx.x;
    int warp = tid >> 5, lane = tid & 31;
    for (int i = tid; i < ZC; i += 256) sz[i] = g_zfull[b * ZC + i];
    __syncthreads();
    for (int j = warp; j < HH; j += 8) {
        const float* w = w_init + (size_t)j * ZC;
        float acc = 0.f;
        for (int k = lane; k < ZC; k += 32) acc += sz[k] * __ldg(w + k);
        acc = warp_sum(acc);
        if (lane == 0) g_h0[0][(size_t)b * HH + j] = acc + b_init[j];
    }
}

__global__ void __launch_bounds__(256) k_zpart(const float* __restrict__ w_ih_g)
{
    __shared__ float sz[ZC];
    int b = blockIdx.x, tid = threadIdx.x;
    int warp = tid >> 5, lane = tid & 31;
    for (int i = tid; i < ZC; i += 256) sz[i] = g_zfull[b * ZC + i];
    __syncthreads();
    for (int j = warp; j < H3; j += 8) {
        const float* w = w_ih_g + (size_t)j * KIN + RR;
        float acc = 0.f;
        for (int k = lane; k < ZC; k += 32) acc += sz[k] * __ldg(w + k);
        acc = warp_sum(acc);
        if (lane == 0) g_zpart[(size_t)b * H3 + j] = acc;
    }
}

// Fold zpart into gi_gx so dec1 reads a single preactivation stream.
__global__ void __launch_bounds__(256) k_addz() {
    int t = blockIdx.x, b = blockIdx.y, tid = threadIdx.x;
    float4* dst = (float4*)(g_gi_gx + ((size_t)t * BB + b) * H3);
    const float4* src = (const float4*)(g_zpart + (size_t)b * H3);
#pragma unroll
    for (int i = 0; i < 3; i++) {
        int e = tid + i * 256;
        float4 d = dst[e], s = src[e];
        d.x += s.x; d.y += s.y; d.z += s.z; d.w += s.w;
        dst[e] = d;
    }
}

// ---------------------------------------------------------------------------
// Final logits + log_softmax (unchanged)
// ---------------------------------------------------------------------------
__global__ void __launch_bounds__(256) k_logits(
    const float* __restrict__ w_out, const float* __restrict__ b_out,
    float* __restrict__ out)
{
    __shared__ __align__(16) float sm[10880];
    const int tid = threadIdx.x, warp = tid >> 5, lane = tid & 31;
    const int m0 = blockIdx.x * 128;
    float* sH = sm;
    float* sW = sm + 5120;

    wmma::fragment<wmma::accumulator, 16, 16, 8, float> c[9];
#pragma unroll
    for (int q = 0; q < 9; q++) wmma::fill_fragment(c[q], 0.f);

    for (int kt = 0; kt < 32; ++kt) {
        const int k0 = kt * 32;
#pragma unroll
        for (int i = 0; i < 4; i++) {
            int e = tid + i * 256;
            int row = e >> 3, kk = (e & 7) << 2;
            *(float4*)(sH + row * 40 + kk) =
                *(const float4*)(g_h1all + (size_t)(m0 + row) * HH + k0 + kk);
        }
#pragma unroll
        for (int i = 0; i < 5; i++) {
            int e = tid + i * 256;
            if (e < 1152) {
                int col = e >> 3, kk = (e & 7) << 2;
                float4 v = make_float4(0.f, 0.f, 0.f, 0.f);
                if (col < RR) v = *(const float4*)(w_out + (size_t)col * HH + k0 + kk);
                *(float4*)(sW + col * 40 + kk) = v;
            }
        }
        __syncthreads();
#pragma unroll
        for (int ks = 0; ks < 4; ks++) {
            wmma::fragment<wmma::matrix_a, 16, 16, 8, wmma::precision::tf32, wmma::row_major> a;
            wmma::load_matrix_sync(a, sH + warp * 16 * 40 + ks * 8, 40);
#pragma unroll
            for (int i = 0; i < a.num_elements; i++) a.x[i] = TF32(a.x[i]);
#pragma unroll
            for (int q = 0; q < 9; q++) {
                wmma::fragment<wmma::matrix_b, 16, 16, 8, wmma::precision::tf32, wmma::col_major> bf;
                wmma::load_matrix_sync(bf, sW + q * 16 * 40 + ks * 8, 40);
#pragma unroll
                for (int i = 0; i < bf.num_elements; i++) bf.x[i] = TF32(bf.x[i]);
                wmma::mma_sync(c[q], a, bf, c[q]);
            }
        }
        __syncthreads();
    }
    float* sG = sm;
    for (int half = 0; half < 2; half++) {
        __syncthreads();
        if ((warp >> 2) == half) {
#pragma unroll
            for (int q = 0; q < 9; q++)
                wmma::store_matrix_sync(sG + (warp & 3) * 16 * 144 + q * 16, c[q], 144,
                                        wmma::mem_row_major);
        }
        __syncthreads();
        for (int rr = warp; rr < 64; rr += 8) {
            int m = m0 + half * 64 + rr;
            float mx = -1e30f;
            for (int j = lane; j < RR; j += 32) {
                float v = sG[rr * 144 + j] + b_out[j];
                mx = fmaxf(mx, v);
            }
#pragma unroll
            for (int off = 16; off > 0; off >>= 1)
                mx = fmaxf(mx, __shfl_xor_sync(0xffffffffu, mx, off));
            float s = 0.f;
            for (int j = lane; j < RR; j += 32)
                s += expf(sG[rr * 144 + j] + b_out[j] - mx);
#pragma unroll
            for (int off = 16; off > 0; off >>= 1)
                s += __shfl_xor_sync(0xffffffffu, s, off);
            float lse = mx + logf(s);
            int b = m & 127, t = m >> 7;
            float* orow = out + ((size_t)b * TT + t) * RR;
            for (int j = lane; j < RR; j += 32)
                orow[j] = sG[rr * 144 + j] + b_out[j] - lse;
        }
    }
}

// ---------------------------------------------------------------------------
extern "C" void kernel_launch(void* const* d_in, const int* in_sizes, int n_in,
                              void* d_out, int out_size) {
    (void)in_sizes; (void)n_in; (void)out_size;
    const float* x       = (const float*)d_in[0];
    const float* chroma  = (const float*)d_in[1];
    const float* eps     = (const float*)d_in[2];
    const float* w_ih_f  = (const float*)d_in[3];
    const float* w_hh_f  = (const float*)d_in[4];
    const float* b_ih_f  = (const float*)d_in[5];
    const float* b_hh_f  = (const float*)d_in[6];
    const float* w_ih_b  = (const float*)d_in[7];
    const float* w_hh_b  = (const float*)d_in[8];
    const float* b_ih_b  = (const float*)d_in[9];
    const float* b_hh_b  = (const float*)d_in[10];
    const float* w_mu    = (const float*)d_in[11];
    const float* b_mu    = (const float*)d_in[12];
    const float* w_var   = (const float*)d_in[13];
    const float* b_var   = (const float*)d_in[14];
    const float* w_init  = (const float*)d_in[15];
    const float* b_init  = (const float*)d_in[16];
    const float* w_ih_g  = (const float*)d_in[17];
    const float* w_hh_g  = (const float*)d_in[18];
    const float* b_ih_g  = (const float*)d_in[19];
    const float* b_hh_g  = (const float*)d_in[20];
    const float* w_ih_g2 = (const float*)d_in[21];
    const float* w_hh_g2 = (const float*)d_in[22];
    const float* b_ih_g2 = (const float*)d_in[23];
    const float* b_hh_g2 = (const float*)d_in[24];
    const float* w_out   = (const float*)d_in[25];
    const float* b_out   = (const float*)d_in[26];
    float* out = (float*)d_out;

    cudaFuncSetAttribute(k_enc_persist, cudaFuncAttributeMaxDynamicSharedMemorySize, SMEM_BYTES);
    cudaFuncSetAttribute(k_dec_persist, cudaFuncAttributeMaxDynamicSharedMemorySize, SMEM_BYTES);

    k_init<<<512, 256>>>();
    k_input_gemm<<<dim3(48, 256, 3), 256>>>(x, w_ih_f, b_ih_f, w_ih_b, b_ih_b,
                                            w_ih_g, b_ih_g);
    k_enc_persist<<<128, 256, SMEM_BYTES>>>(w_hh_f, b_hh_f, w_hh_b, b_hh_b);
    k_head<<<BB, 256>>>(chroma, eps, w_mu, b_mu, w_var, b_var, out);
    k_hx0<<<BB, 256>>>(w_init, b_init);
    k_zpart<<<BB, 256>>>(w_ih_g);
    k_addz<<<dim3(TT, BB), 256>>>();
    k_dec_persist<<<128, 256, SMEM_BYTES>>>(w_hh_g, b_hh_g, w_ih_g2, w_hh_g2,
                                            b_ih_g2, b_hh_g2);
    k_logits<<<256, 256>>>(w_out, b_out, out);
}

// round 12
// speedup vs baseline: 4.9033x; 2.3825x over previous
#include <cuda_runtime.h>
#include <cuda_fp16.h>
#include <mma.h>
#include <cstdint>
#include <cstddef>
#include <math.h>

using namespace nvcuda;

#define BB 128
#define TT 256
#define RR 130
#define HH 1024
#define H3 3072
#define ZZ2 256
#define CC 24
#define ZC 280
#define KIN 410

// fp16 persistent-step shared memory layout (in halfs)
#define HLDH 136                  // sH row stride (128 + 8 pad)
#define WLDH 1040                 // resident W row stride (1024 + 16 pad)
#define CHK 128                   // K per chunk
#define NCH 8                     // chunks per 1024-K GEMM
#define OFF_SW 0                  // 48 x 1040 resident W
#define SW_H (48 * WLDH)          // 49920
#define OFF_SH SW_H               // double-buffered A staging
#define SH_BUF (128 * HLDH)       // 17408
#define OFF_SWS (OFF_SH + 2 * SH_BUF)   // 84736: dec2 streamed-W staging
#define SWS_BUF (48 * HLDH)       // 6528
#define OFF_SB (OFF_SWS + 2 * SWS_BUF)  // 97792 (halfs) -> float bias region
#define SMEMH (OFF_SB + 192)
#define SMEM_BYTES (SMEMH * 2)

static constexpr size_t GI_SZ = (size_t)TT * BB * H3;

__device__ __align__(128) float g_gi_f[GI_SZ];
__device__ __align__(128) float g_gi_b[GI_SZ];
__device__ __align__(128) float g_gi_gx[GI_SZ];
__device__ __align__(128) float g_h1all[(size_t)TT * BB * HH];
__device__ __align__(128) float g_zpart[BB * H3];
__device__ __align__(128) float g_zfull[BB * ZC];
__device__ __align__(128) float g_hf[2][BB * HH];
__device__ __align__(128) float g_hb[2][BB * HH];
__device__ __align__(128) float g_h0[2][BB * HH];
__device__ __align__(128) float g_h1[2][BB * HH];
// fp16 mirrors (MMA inputs)
__device__ __align__(128) __half g_hfh[2][BB * HH];
__device__ __align__(128) __half g_hbh[2][BB * HH];
__device__ __align__(128) __half g_h0h[2][BB * HH];
__device__ __align__(128) __half g_h1h[2][BB * HH];
__device__ __align__(128) __half g_wih2[(size_t)H3 * HH];   // w_ih_g2 in fp16

// software grid barriers (reset by k_init each invocation)
__device__ volatile int g_gen_ef; __device__ unsigned int g_cnt_ef;
__device__ volatile int g_gen_eb; __device__ unsigned int g_cnt_eb;
__device__ volatile int g_gen_1;  __device__ unsigned int g_cnt_1;
__device__ volatile int g_gen_2;  __device__ unsigned int g_cnt_2;

static constexpr size_t OFF_MU  = (size_t)BB * TT * RR;
static constexpr size_t OFF_STD = OFF_MU + (size_t)BB * ZZ2;
static constexpr size_t OFF_Z   = OFF_STD + (size_t)BB * ZZ2;

__device__ __forceinline__ float sigf(float v) { return 1.f / (1.f + expf(-v)); }
#define TF32(x) wmma::__float_to_tf32(x)

__device__ __forceinline__ float warp_sum(float v) {
#pragma unroll
    for (int off = 16; off > 0; off >>= 1)
        v += __shfl_xor_sync(0xffffffffu, v, off);
    return v;
}

// ---- cp.async helpers ------------------------------------------------------
__device__ __forceinline__ void cpa16(uint32_t dst, const void* src) {
    asm volatile("cp.async.cg.shared.global [%0], [%1], 16;" :: "r"(dst), "l"(src));
}
__device__ __forceinline__ void cpa_commit() { asm volatile("cp.async.commit_group;"); }
template <int N> __device__ __forceinline__ void cpa_wait() {
    asm volatile("cp.async.wait_group %0;" :: "n"(N));
}

// ---------------------------------------------------------------------------
__global__ void k_init() {
    int i = blockIdx.x * blockDim.x + threadIdx.x;
    if (i < BB * HH) {
        g_hf[0][i] = 0.f; g_hb[0][i] = 0.f;
        g_hfh[0][i] = __float2half_rn(0.f);
        g_hbh[0][i] = __float2half_rn(0.f);
    }
    if (i == 0) {
        g_gen_ef = 0; g_cnt_ef = 0;
        g_gen_eb = 0; g_cnt_eb = 0;
        g_gen_1 = 0;  g_cnt_1 = 0;
        g_gen_2 = 0;  g_cnt_2 = 0;
    }
}

// convert w_ih_g2 to fp16 once (grid H3 blocks x 256 threads, 4 elems each)
__global__ void k_convw(const float* __restrict__ w) {
    size_t i = ((size_t)blockIdx.x * HH) + threadIdx.x * 4;
    float4 v = *(const float4*)(w + i);
    __half2 a = __floats2half2_rn(v.x, v.y);
    __half2 b = __floats2half2_rn(v.z, v.w);
    *(__half2*)(g_wih2 + i) = a;
    *(__half2*)(g_wih2 + i + 2) = b;
}

// generation barrier over nb co-resident blocks; target strictly increasing
__device__ __forceinline__ void group_barrier(unsigned int* cnt, volatile int* gen,
                                              int target, int nb) {
    __syncthreads();
    if (threadIdx.x == 0) {
        __threadfence();
        if (atomicAdd(cnt, 1u) == (unsigned)(nb - 1)) {
            atomicExch(cnt, 0u);
            __threadfence();
            *gen = target;
        } else {
            while (*gen < target) __nanosleep(32);
            __threadfence();
        }
    }
    __syncthreads();
}

__device__ __forceinline__ void wait_gen(volatile int* gen, int target) {
    if (threadIdx.x == 0) {
        while (*gen < target) __nanosleep(32);
        __threadfence();
    }
    __syncthreads();
}

// ---------------------------------------------------------------------------
// Input-side GEMMs for all timesteps: gi = A @ W^T + b_ih  (tf32, unchanged)
// ---------------------------------------------------------------------------
__global__ void __launch_bounds__(256) k_input_gemm(
    const float* __restrict__ x,
    const float* __restrict__ w_f, const float* __restrict__ bi_f,
    const float* __restrict__ w_b, const float* __restrict__ bi_b,
    const float* __restrict__ w_g, const float* __restrict__ bi_g)
{
    __shared__ __align__(16) float sm[8192];
    const int tid = threadIdx.x;
    const int warp = tid >> 5;
    const int wm = warp >> 1, wn = warp & 1;

    const int mode = blockIdx.z;
    const float* W  = (mode == 0) ? w_f : (mode == 1) ? w_b : w_g;
    const float* bi = (mode == 0) ? bi_f : (mode == 1) ? bi_b : bi_g;
    float* gout = (mode == 0) ? g_gi_f : (mode == 1) ? g_gi_b : g_gi_gx;
    const int wstride = (mode == 2) ? KIN : RR;

    const int m0 = blockIdx.y * 128;
    const int n0 = blockIdx.x * 64;
    float* sA = sm;
    float* sB = sm + 3072;

    wmma::fragment<wmma::accumulator, 16, 16, 8, float> c[2][2];
#pragma unroll
    for (int s = 0; s < 2; s++)
#pragma unroll
        for (int s2 = 0; s2 < 2; s2++) wmma::fill_fragment(c[s][s2], 0.f);

    for (int kt = 0; kt < 9; ++kt) {
        const int k0 = kt * 16;
#pragma unroll
        for (int i = 0; i < 8; i++) {
            int e = tid + i * 256;
            int r = e >> 4, kk = e & 15;
            int m = m0 + r, k = k0 + kk;
            int tstep = m >> 7, b = m & 127;
            float v = 0.f;
            if (k < RR) {
                if (mode < 2) v = x[(size_t)b * TT * RR + (size_t)tstep * RR + k];
                else if (tstep == 0) v = (k == RR - 1) ? 1.f : 0.f;
                else v = x[(size_t)b * TT * RR + (size_t)(tstep - 1) * RR + k];
            }
            sA[r * 24 + kk] = v;
        }
#pragma unroll
        for (int i = 0; i < 4; i++) {
            int e = tid + i * 256;
            int col = e >> 4, kk = e & 15;
            int n = n0 + col, k = k0 + kk;
            sB[col * 24 + kk] = (k < RR) ? W[(size_t)n * wstride + k] : 0.f;
        }
        __syncthreads();
#pragma unroll
        for (int ks = 0; ks < 2; ks++) {
            wmma::fragment<wmma::matrix_a, 16, 16, 8, wmma::precision::tf32, wmma::row_major> a[2];
            wmma::fragment<wmma::matrix_b, 16, 16, 8, wmma::precision::tf32, wmma::col_major> bf[2];
#pragma unroll
            for (int s = 0; s < 2; s++) {
                wmma::load_matrix_sync(a[s], sA + (wm * 32 + s * 16) * 24 + ks * 8, 24);
#pragma unroll
                for (int i = 0; i < a[s].num_elements; i++) a[s].x[i] = TF32(a[s].x[i]);
            }
#pragma unroll
            for (int s2 = 0; s2 < 2; s2++) {
                wmma::load_matrix_sync(bf[s2], sB + (wn * 32 + s2 * 16) * 24 + ks * 8, 24);
#pragma unroll
                for (int i = 0; i < bf[s2].num_elements; i++) bf[s2].x[i] = TF32(bf[s2].x[i]);
            }
#pragma unroll
            for (int s = 0; s < 2; s++)
#pragma unroll
                for (int s2 = 0; s2 < 2; s2++)
                    wmma::mma_sync(c[s][s2], a[s], bf[s2], c[s][s2]);
        }
        __syncthreads();
    }
#pragma unroll
    for (int s = 0; s < 2; s++)
#pragma unroll
        for (int s2 = 0; s2 < 2; s2++)
            wmma::store_matrix_sync(sm + (wm * 32 + s * 16) * 64 + (wn * 32 + s2 * 16),
                                    c[s][s2], 64, wmma::mem_row_major);
    __syncthreads();
#pragma unroll
    for (int i = 0; i < 8; i++) {
        int e = tid + i * 256;
        int r = e >> 4, c4 = (e & 15) << 2;
        int n = n0 + c4;
        float4 v = *(float4*)(sm + r * 64 + c4);
        v.x += bi[n]; v.y += bi[n + 1]; v.z += bi[n + 2]; v.w += bi[n + 3];
        *(float4*)(gout + (size_t)(m0 + r) * H3 + n) = v;
    }
}

// ---------------------------------------------------------------------------
// Load a 48-row W slice into resident SMEM as fp16, [col][k], ld WLDH.
// ---------------------------------------------------------------------------
__device__ __forceinline__ void load_w_res_h(const float* __restrict__ W,
                                             __half* __restrict__ sW, int ctile) {
    const int tid = threadIdx.x;
#pragma unroll 4
    for (int i = 0; i < 48; i++) {
        int e = tid + (i << 8);
        int col = e >> 8, k4 = (e & 255) << 2;
        int q = col >> 4, jl = col & 15;
        float4 v = *(const float4*)(W + (size_t)(q * HH + ctile * 16 + jl) * HH + k4);
        __half2 a = __floats2half2_rn(v.x, v.y);
        __half2 b = __floats2half2_rn(v.z, v.w);
        *(__half2*)(sW + col * WLDH + k4) = a;
        *(__half2*)(sW + col * WLDH + k4 + 2) = b;
    }
}

// stage one 128x128 fp16 A chunk via cp.async (8 x 16B per thread)
__device__ __forceinline__ void stage_h(uint32_t sh_addr, const __half* __restrict__ hsrc, int c) {
    const int tid = threadIdx.x;
#pragma unroll
    for (int i = 0; i < 8; i++) {
        int u = tid + (i << 8);        // 0..2047 16B-units
        int row = u >> 4, un = u & 15;
        cpa16(sh_addr + (uint32_t)(row * HLDH + un * 8) * 2,
              hsrc + (size_t)row * HH + c * CHK + un * 8);
    }
}

// stage one 48x128 fp16 streamed-W chunk via cp.async (rows = gate cols)
__device__ __forceinline__ void stage_w(uint32_t sw_addr, const __half* __restrict__ wsrc,
                                        int ctile, int c) {
    const int tid = threadIdx.x;
#pragma unroll
    for (int i = 0; i < 3; i++) {
        int u = tid + (i << 8);
        if (u < 768) {
            int col = u >> 4, un = u & 15;
            int g = (col >> 4) * HH + ctile * 16 + (col & 15);
            cpa16(sw_addr + (uint32_t)(col * HLDH + un * 8) * 2,
                  wsrc + (size_t)g * HH + c * CHK + un * 8);
        }
    }
}

// one chunk of MMAs: A 16x128 per warp from sH, B 48 cols from resident sW
__device__ __forceinline__ void mma_chunk_res(
    wmma::fragment<wmma::accumulator, 16, 16, 16, float>* acc,
    const __half* __restrict__ sH, const __half* __restrict__ sW, int c)
{
    const int warp = threadIdx.x >> 5;
#pragma unroll
    for (int ks = 0; ks < 8; ks++) {
        wmma::fragment<wmma::matrix_a, 16, 16, 16, __half, wmma::row_major> a;
        wmma::load_matrix_sync(a, sH + warp * 16 * HLDH + ks * 16, HLDH);
#pragma unroll
        for (int q = 0; q < 3; q++) {
            wmma::fragment<wmma::matrix_b, 16, 16, 16, __half, wmma::col_major> b;
            wmma::load_matrix_sync(b, sW + (q * 16) * WLDH + c * CHK + ks * 16, WLDH);
            wmma::mma_sync(acc[q], a, b, acc[q]);
        }
    }
}

// one chunk of MMAs with streamed B (ld HLDH)
__device__ __forceinline__ void mma_chunk_str(
    wmma::fragment<wmma::accumulator, 16, 16, 16, float>* acc,
    const __half* __restrict__ sH, const __half* __restrict__ sWs)
{
    const int warp = threadIdx.x >> 5;
#pragma unroll
    for (int ks = 0; ks < 8; ks++) {
        wmma::fragment<wmma::matrix_a, 16, 16, 16, __half, wmma::row_major> a;
        wmma::load_matrix_sync(a, sH + warp * 16 * HLDH + ks * 16, HLDH);
#pragma unroll
        for (int q = 0; q < 3; q++) {
            wmma::fragment<wmma::matrix_b, 16, 16, 16, __half, wmma::col_major> b;
            wmma::load_matrix_sync(b, sWs + (q * 16) * HLDH + ks * 16, HLDH);
            wmma::mma_sync(acc[q], a, b, acc[q]);
        }
    }
}

// ---------------------------------------------------------------------------
// GRU step (fp16 pipeline): gh = h_old @ Wres^T + bhh, fused gates.
// ---------------------------------------------------------------------------
__device__ __forceinline__ void gru_step_f16(
    const float* __restrict__ h_old, const __half* __restrict__ h_oldh,
    float* __restrict__ h_new, __half* __restrict__ h_newh,
    const __half* __restrict__ sW, const float* __restrict__ sB,
    const float* __restrict__ gi1, int ctile,
    __half* __restrict__ sH, uint32_t sH_addr)
{
    const int tid = threadIdx.x, warp = tid >> 5;

    // epilogue operand prefetch (L2/DRAM latency hidden under the GEMM)
    float pgi[24], pho[8];
#pragma unroll
    for (int i = 0; i < 8; i++) {
        int e = tid + (i << 8);
        int row = e >> 4, jl = e & 15, j = ctile * 16 + jl;
        const float* gr = gi1 + (size_t)row * H3 + j;
        pgi[i * 3 + 0] = __ldg(gr);
        pgi[i * 3 + 1] = __ldg(gr + HH);
        pgi[i * 3 + 2] = __ldg(gr + 2 * HH);
        pho[i] = __ldcg(h_old + (size_t)row * HH + j);
    }

    wmma::fragment<wmma::accumulator, 16, 16, 16, float> acc[3];
#pragma unroll
    for (int q = 0; q < 3; q++) wmma::fill_fragment(acc[q], 0.f);

    stage_h(sH_addr, h_oldh, 0);
    cpa_commit();
    for (int c = 0; c < NCH; c++) {
        if (c + 1 < NCH) {
            stage_h(sH_addr + ((uint32_t)((c + 1) & 1)) * SH_BUF * 2, h_oldh, c + 1);
            cpa_commit();
            cpa_wait<1>();
        } else {
            cpa_wait<0>();
        }
        __syncthreads();
        mma_chunk_res(acc, sH + (c & 1) * SH_BUF, sW, c);
        __syncthreads();
    }

    float* sG = (float*)sH;   // 128 x 48 fp32, overlays staging buffers
#pragma unroll
    for (int q = 0; q < 3; q++)
        wmma::store_matrix_sync(sG + warp * 16 * 48 + q * 16, acc[q], 48, wmma::mem_row_major);
    __syncthreads();
#pragma unroll
    for (int i = 0; i < 8; i++) {
        int e = tid + (i << 8);
        int row = e >> 4, jl = e & 15;
        int j = ctile * 16 + jl;
        float hr = sG[row * 48 + jl]      + sB[jl];
        float hz = sG[row * 48 + 16 + jl] + sB[16 + jl];
        float hn = sG[row * 48 + 32 + jl] + sB[32 + jl];
        float r = sigf(pgi[i * 3 + 0] + hr);
        float u = sigf(pgi[i * 3 + 1] + hz);
        float n = tanhf(pgi[i * 3 + 2] + r * hn);
        float o = (1.f - u) * n + u * pho[i];
        h_new[(size_t)row * HH + j] = o;
        h_newh[(size_t)row * HH + j] = __float2half_rn(o);
    }
    __syncthreads();   // sG reuse protection for next step's staging
}

// ---------------------------------------------------------------------------
// Persistent encoder: 64 blocks/direction, per-direction barriers.
// ---------------------------------------------------------------------------
__global__ void __launch_bounds__(256) k_enc_persist(
    const float* __restrict__ w_hh_f, const float* __restrict__ b_hh_f,
    const float* __restrict__ w_hh_b, const float* __restrict__ b_hh_b)
{
    extern __shared__ __align__(16) __half smh[];
    __half* sW = smh + OFF_SW;
    __half* sH = smh + OFF_SH;
    float* sB = (float*)(smh + OFF_SB);
    uint32_t sH_addr = (uint32_t)__cvta_generic_to_shared(sH);
    const int tid = threadIdx.x;
    const int dir = blockIdx.x >> 6, ctile = blockIdx.x & 63;
    const float* W   = dir ? w_hh_b : w_hh_f;
    const float* bhh = dir ? b_hh_b : b_hh_f;
    unsigned int* cnt = dir ? &g_cnt_eb : &g_cnt_ef;
    volatile int* gen = dir ? &g_gen_eb : &g_gen_ef;

    load_w_res_h(W, sW, ctile);
    if (tid < 48) {
        int q = tid >> 4, jl = tid & 15;
        sB[tid] = bhh[q * HH + ctile * 16 + jl];
    }
    __syncthreads();

    for (int t = 0; t < TT; t++) {
        const int p = t & 1;
        const float* h_old  = dir ? g_hb[p] : g_hf[p];
        const __half* h_oldh = dir ? g_hbh[p] : g_hfh[p];
        float* h_new  = dir ? g_hb[1 - p] : g_hf[1 - p];
        __half* h_newh = dir ? g_hbh[1 - p] : g_hfh[1 - p];
        const float* gi = dir ? g_gi_b + (size_t)(TT - 1 - t) * BB * H3
                              : g_gi_f + (size_t)t * BB * H3;
        gru_step_f16(h_old, h_oldh, h_new, h_newh, sW, sB, gi, ctile, sH, sH_addr);
        group_barrier(cnt, gen, t + 1, 64);
    }
}

// ---------------------------------------------------------------------------
// Decoder cell2 step (fp16): ci = h0n @ Wi^T (streamed), ch = h1p @ Wh^T (res)
// ---------------------------------------------------------------------------
__device__ __forceinline__ void dec2_step_f16(
    const float* __restrict__ h1p, const __half* __restrict__ h0nh,
    const __half* __restrict__ h1ph,
    float* __restrict__ h1n, __half* __restrict__ h1nh,
    const __half* __restrict__ sWh, const float* __restrict__ sB,
    int ctile, __half* __restrict__ sH, uint32_t sH_addr,
    __half* __restrict__ sWs, uint32_t sWs_addr, int t)
{
    const int tid = threadIdx.x, warp = tid >> 5;

    float pho[8];
#pragma unroll
    for (int i = 0; i < 8; i++) {
        int e = tid + (i << 8);
        int row = e >> 4, jl = e & 15;
        pho[i] = __ldcg(h1p + (size_t)row * HH + ctile * 16 + jl);
    }

    wmma::fragment<wmma::accumulator, 16, 16, 16, float> ai[3], ah[3];
#pragma unroll
    for (int q = 0; q < 3; q++) { wmma::fill_fragment(ai[q], 0.f); wmma::fill_fragment(ah[q], 0.f); }

    // ---- phase 1: input side (h0n x streamed Wi) ----
    stage_h(sH_addr, h0nh, 0);
    stage_w(sWs_addr, g_wih2, ctile, 0);
    cpa_commit();
    for (int c = 0; c < NCH; c++) {
        if (c + 1 < NCH) {
            stage_h(sH_addr + ((uint32_t)((c + 1) & 1)) * SH_BUF * 2, h0nh, c + 1);
            stage_w(sWs_addr + ((uint32_t)((c + 1) & 1)) * SWS_BUF * 2, g_wih2, ctile, c + 1);
            cpa_commit();
            cpa_wait<1>();
        } else {
            cpa_wait<0>();
        }
        __syncthreads();
        mma_chunk_str(ai, sH + (c & 1) * SH_BUF, sWs + (c & 1) * SWS_BUF);
        __syncthreads();
    }

    // ---- phase 2: hidden side (h1p x resident Wh) ----
    stage_h(sH_addr, h1ph, 0);
    cpa_commit();
    for (int c = 0; c < NCH; c++) {
        if (c + 1 < NCH) {
            stage_h(sH_addr + ((uint32_t)((c + 1) & 1)) * SH_BUF * 2, h1ph, c + 1);
            cpa_commit();
            cpa_wait<1>();
        } else {
            cpa_wait<0>();
        }
        __syncthreads();
        mma_chunk_res(ah, sH + (c & 1) * SH_BUF, sWh, c);
        __syncthreads();
    }

    // ---- epilogue ----
    float* sG = (float*)sH;
#pragma unroll
    for (int q = 0; q < 3; q++)
        wmma::store_matrix_sync(sG + warp * 16 * 48 + q * 16, ai[q], 48, wmma::mem_row_major);
    __syncthreads();
    float vvi[24];
#pragma unroll
    for (int i = 0; i < 8; i++) {
        int e = tid + (i << 8); int row = e >> 4, jl = e & 15;
        vvi[i * 3 + 0] = sG[row * 48 + jl];
        vvi[i * 3 + 1] = sG[row * 48 + 16 + jl];
        vvi[i * 3 + 2] = sG[row * 48 + 32 + jl];
    }
    __syncthreads();
#pragma unroll
    for (int q = 0; q < 3; q++)
        wmma::store_matrix_sync(sG + warp * 16 * 48 + q * 16, ah[q], 48, wmma::mem_row_major);
    __syncthreads();
#pragma unroll
    for (int i = 0; i < 8; i++) {
        int e = tid + (i << 8);
        int row = e >> 4, jl = e & 15;
        int j = ctile * 16 + jl;
        float ir  = vvi[i * 3 + 0] + sB[jl];
        float iz  = vvi[i * 3 + 1] + sB[16 + jl];
        float in_ = vvi[i * 3 + 2] + sB[32 + jl];
        float hr = sG[row * 48 + jl]      + sB[48 + jl];
        float hz = sG[row * 48 + 16 + jl] + sB[64 + jl];
        float hn = sG[row * 48 + 32 + jl] + sB[80 + jl];
        float r = sigf(ir + hr);
        float u = sigf(iz + hz);
        float n = tanhf(in_ + r * hn);
        float o = (1.f - u) * n + u * pho[i];
        h1n[(size_t)row * HH + j] = o;
        h1nh[(size_t)row * HH + j] = __float2half_rn(o);
        g_h1all[((size_t)t * BB + row) * HH + j] = o;
    }
    __syncthreads();
}

// ---------------------------------------------------------------------------
// Persistent decoder: blocks 0..63 = cell1 chain, 64..127 = cell2 chain.
// ---------------------------------------------------------------------------
__global__ void __launch_bounds__(256) k_dec_persist(
    const float* __restrict__ w_hh_g,  const float* __restrict__ b_hh_g,
    const float* __restrict__ w_hh_g2,
    const float* __restrict__ b_ih_g2, const float* __restrict__ b_hh_g2)
{
    extern __shared__ __align__(16) __half smh[];
    __half* sW = smh + OFF_SW;
    __half* sH = smh + OFF_SH;
    __half* sWs = smh + OFF_SWS;
    float* sB = (float*)(smh + OFF_SB);
    uint32_t sH_addr = (uint32_t)__cvta_generic_to_shared(sH);
    uint32_t sWs_addr = (uint32_t)__cvta_generic_to_shared(sWs);
    const int tid = threadIdx.x;

    if (blockIdx.x < 64) {
        const int ctile = blockIdx.x;
        load_w_res_h(w_hh_g, sW, ctile);
        if (tid < 48) {
            int q = tid >> 4, jl = tid & 15;
            sB[tid] = b_hh_g[q * HH + ctile * 16 + jl];
        }
        __syncthreads();
        for (int t = 0; t < TT; t++) {
            if (t >= 2) wait_gen(&g_gen_2, t - 1);   // buffer reuse vs cell2 readers
            const int p = t & 1;
            gru_step_f16(g_h0[p], g_h0h[p], g_h0[1 - p], g_h0h[1 - p], sW, sB,
                         g_gi_gx + (size_t)t * BB * H3, ctile, sH, sH_addr);
            group_barrier(&g_cnt_1, &g_gen_1, t + 1, 64);
        }
    } else {
        const int ctile = blockIdx.x - 64;
        load_w_res_h(w_hh_g2, sW, ctile);
        if (tid < 48) {
            int q = tid >> 4, jl = tid & 15;
            sB[tid]      = b_ih_g2[q * HH + ctile * 16 + jl];
            sB[48 + tid] = b_hh_g2[q * HH + ctile * 16 + jl];
        }
        __syncthreads();
        for (int t = 0; t < TT; t++) {
            wait_gen(&g_gen_1, t + 1);               // h0n(t) ready
            const int p = t & 1;
            const float* h1p  = (t == 0) ? g_h0[1] : g_h1[p];
            const __half* h1ph = (t == 0) ? g_h0h[1] : g_h1h[p];
            dec2_step_f16(h1p, g_h0h[1 - p], h1ph, g_h1[1 - p], g_h1h[1 - p],
                          sW, sB, ctile, sH, sH_addr, sWs, sWs_addr, t);
            group_barrier(&g_cnt_2, &g_gen_2, t + 1, 64);
        }
    }
}

// ---------------------------------------------------------------------------
// mu / std / z heads — warp-dot, coalesced weight reads.
// ---------------------------------------------------------------------------
__global__ void __launch_bounds__(256) k_head(
    const float* __restrict__ chroma, const float* __restrict__ eps,
    const float* __restrict__ w_mu, const float* __restrict__ b_mu,
    const float* __restrict__ w_var, const float* __restrict__ b_var,
    float* __restrict__ out)
{
    __shared__ float sh[2048];
    __shared__ float sacc[2 * ZZ2];
    int b = blockIdx.x, tid = threadIdx.x;
    int warp = tid >> 5, lane = tid & 31;
    for (int i = tid; i < HH; i += 256) {
        sh[i] = g_hf[0][(size_t)b * HH + i];
        sh[HH + i] = g_hb[0][(size_t)b * HH + i];
    }
    __syncthreads();
    for (int task = warp; task < 2 * ZZ2; task += 8) {
        int head = task >> 8, j = task & 255;
        const float* w = (head ? w_var : w_mu) + (size_t)j * 2048;
        float acc = 0.f;
        for (int k = lane; k < 2048; k += 32) acc += sh[k] * __ldg(w + k);
        acc = warp_sum(acc);
        if (lane == 0) sacc[task] = acc + (head ? b_var[j] : b_mu[j]);
    }
    __syncthreads();
    if (tid < ZZ2) {
        int j = tid;
        float accm = sacc[j];
        float std = expf(sacc[ZZ2 + j]);
        float z = accm + std * eps[(size_t)b * ZZ2 + j];
        g_zfull[b * ZC + j] = z;
        out[OFF_MU + (size_t)b * ZZ2 + j] = accm;
        out[OFF_STD + (size_t)b * ZZ2 + j] = std;
        out[OFF_Z + (size_t)b * ZC + j] = z;
        if (j < CC) {
            float cv = chroma[b * CC + j];
            g_zfull[b * ZC + ZZ2 + j] = cv;
            out[OFF_Z + (size_t)b * ZC + ZZ2 + j] = cv;
        }
    }
}

__global__ void __launch_bounds__(256) k_hx0(
    const float* __restrict__ w_init, const float* __restrict__ b_init)
{
    __shared__ float sz[ZC];
    int b = blockIdx.x, tid = threadIdx.x;
    int warp = tid >> 5, lane = tid & 31;
    for (int i = tid; i < ZC; i += 256) sz[i] = g_zfull[b * ZC + i];
    __syncthreads();
    for (int j = warp; j < HH; j += 8) {
        const float* w = w_init + (size_t)j * ZC;
        float acc = 0.f;
        for (int k = lane; k < ZC; k += 32) acc += sz[k] * __ldg(w + k);
        acc = warp_sum(acc);
        if (lane == 0) {
            float v = acc + b_init[j];
            g_h0[0][(size_t)b * HH + j] = v;
            g_h0h[0][(size_t)b * HH + j] = __float2half_rn(v);
        }
    }
}

__global__ void __launch_bounds__(256) k_zpart(const float* __restrict__ w_ih_g)
{
    __shared__ float sz[ZC];
    int b = blockIdx.x, tid = threadIdx.x;
    int warp = tid >> 5, lane = tid & 31;
    for (int i = tid; i < ZC; i += 256) sz[i] = g_zfull[b * ZC + i];
    __syncthreads();
    for (int j = warp; j < H3; j += 8) {
        const float* w = w_ih_g + (size_t)j * KIN + RR;
        float acc = 0.f;
        for (int k = lane; k < ZC; k += 32) acc += sz[k] * __ldg(w + k);
        acc = warp_sum(acc);
        if (lane == 0) g_zpart[(size_t)b * H3 + j] = acc;
    }
}

// Fold zpart into gi_gx so dec1 reads a single preactivation stream.
__global__ void __launch_bounds__(256) k_addz() {
    int t = blockIdx.x, b = blockIdx.y, tid = threadIdx.x;
    float4* dst = (float4*)(g_gi_gx + ((size_t)t * BB + b) * H3);
    const float4* src = (const float4*)(g_zpart + (size_t)b * H3);
#pragma unroll
    for (int i = 0; i < 3; i++) {
        int e = tid + i * 256;
        float4 d = dst[e], s = src[e];
        d.x += s.x; d.y += s.y; d.z += s.z; d.w += s.w;
        dst[e] = d;
    }
}

// ---------------------------------------------------------------------------
// Final logits + log_softmax (tf32, unchanged)
// ---------------------------------------------------------------------------
__global__ void __launch_bounds__(256) k_logits(
    const float* __restrict__ w_out, const float* __restrict__ b_out,
    float* __restrict__ out)
{
    __shared__ __align__(16) float sm[10880];
    const int tid = threadIdx.x, warp = tid >> 5, lane = tid & 31;
    const int m0 = blockIdx.x * 128;
    float* sH = sm;
    float* sW = sm + 5120;

    wmma::fragment<wmma::accumulator, 16, 16, 8, float> c[9];
#pragma unroll
    for (int q = 0; q < 9; q++) wmma::fill_fragment(c[q], 0.f);

    for (int kt = 0; kt < 32; ++kt) {
        const int k0 = kt * 32;
#pragma unroll
        for (int i = 0; i < 4; i++) {
            int e = tid + i * 256;
            int row = e >> 3, kk = (e & 7) << 2;
            *(float4*)(sH + row * 40 + kk) =
                *(const float4*)(g_h1all + (size_t)(m0 + row) * HH + k0 + kk);
        }
#pragma unroll
        for (int i = 0; i < 5; i++) {
            int e = tid + i * 256;
            if (e < 1152) {
                int col = e >> 3, kk = (e & 7) << 2;
                float4 v = make_float4(0.f, 0.f, 0.f, 0.f);
                if (col < RR) v = *(const float4*)(w_out + (size_t)col * HH + k0 + kk);
                *(float4*)(sW + col * 40 + kk) = v;
            }
        }
        __syncthreads();
#pragma unroll
        for (int ks = 0; ks < 4; ks++) {
            wmma::fragment<wmma::matrix_a, 16, 16, 8, wmma::precision::tf32, wmma::row_major> a;
            wmma::load_matrix_sync(a, sH + warp * 16 * 40 + ks * 8, 40);
#pragma unroll
            for (int i = 0; i < a.num_elements; i++) a.x[i] = TF32(a.x[i]);
#pragma unroll
            for (int q = 0; q < 9; q++) {
                wmma::fragment<wmma::matrix_b, 16, 16, 8, wmma::precision::tf32, wmma::col_major> bf;
                wmma::load_matrix_sync(bf, sW + q * 16 * 40 + ks * 8, 40);
#pragma unroll
                for (int i = 0; i < bf.num_elements; i++) bf.x[i] = TF32(bf.x[i]);
                wmma::mma_sync(c[q], a, bf, c[q]);
            }
        }
        __syncthreads();
    }
    float* sG = sm;
    for (int half = 0; half < 2; half++) {
        __syncthreads();
        if ((warp >> 2) == half) {
#pragma unroll
            for (int q = 0; q < 9; q++)
                wmma::store_matrix_sync(sG + (warp & 3) * 16 * 144 + q * 16, c[q], 144,
                                        wmma::mem_row_major);
        }
        __syncthreads();
        for (int rr = warp; rr < 64; rr += 8) {
            int m = m0 + half * 64 + rr;
            float mx = -1e30f;
            for (int j = lane; j < RR; j += 32) {
                float v = sG[rr * 144 + j] + b_out[j];
                mx = fmaxf(mx, v);
            }
#pragma unroll
            for (int off = 16; off > 0; off >>= 1)
                mx = fmaxf(mx, __shfl_xor_sync(0xffffffffu, mx, off));
            float s = 0.f;
            for (int j = lane; j < RR; j += 32)
                s += expf(sG[rr * 144 + j] + b_out[j] - mx);
#pragma unroll
            for (int off = 16; off > 0; off >>= 1)
                s += __shfl_xor_sync(0xffffffffu, s, off);
            float lse = mx + logf(s);
            int b = m & 127, t = m >> 7;
            float* orow = out + ((size_t)b * TT + t) * RR;
            for (int j = lane; j < RR; j += 32)
                orow[j] = sG[rr * 144 + j] + b_out[j] - lse;
        }
    }
}

// ---------------------------------------------------------------------------
extern "C" void kernel_launch(void* const* d_in, const int* in_sizes, int n_in,
                              void* d_out, int out_size) {
    (void)in_sizes; (void)n_in; (void)out_size;
    const float* x       = (const float*)d_in[0];
    const float* chroma  = (const float*)d_in[1];
    const float* eps     = (const float*)d_in[2];
    const float* w_ih_f  = (const float*)d_in[3];
    const float* w_hh_f  = (const float*)d_in[4];
    const float* b_ih_f  = (const float*)d_in[5];
    const float* b_hh_f  = (const float*)d_in[6];
    const float* w_ih_b  = (const float*)d_in[7];
    const float* w_hh_b  = (const float*)d_in[8];
    const float* b_ih_b  = (const float*)d_in[9];
    const float* b_hh_b  = (const float*)d_in[10];
    const float* w_mu    = (const float*)d_in[11];
    const float* b_mu    = (const float*)d_in[12];
    const float* w_var   = (const float*)d_in[13];
    const float* b_var   = (const float*)d_in[14];
    const float* w_init  = (const float*)d_in[15];
    const float* b_init  = (const float*)d_in[16];
    const float* w_ih_g  = (const float*)d_in[17];
    const float* w_hh_g  = (const float*)d_in[18];
    const float* b_ih_g  = (const float*)d_in[19];
    const float* b_hh_g  = (const float*)d_in[20];
    const float* w_ih_g2 = (const float*)d_in[21];
    const float* w_hh_g2 = (const float*)d_in[22];
    const float* b_ih_g2 = (const float*)d_in[23];
    const float* b_hh_g2 = (const float*)d_in[24];
    const float* w_out   = (const float*)d_in[25];
    const float* b_out   = (const float*)d_in[26];
    float* out = (float*)d_out;

    cudaFuncSetAttribute(k_enc_persist, cudaFuncAttributeMaxDynamicSharedMemorySize, SMEM_BYTES);
    cudaFuncSetAttribute(k_dec_persist, cudaFuncAttributeMaxDynamicSharedMemorySize, SMEM_BYTES);

    k_init<<<512, 256>>>();
    k_convw<<<H3, 256>>>(w_ih_g2);
    k_input_gemm<<<dim3(48, 256, 3), 256>>>(x, w_ih_f, b_ih_f, w_ih_b, b_ih_b,
                                            w_ih_g, b_ih_g);
    k_enc_persist<<<128, 256, SMEM_BYTES>>>(w_hh_f, b_hh_f, w_hh_b, b_hh_b);
    k_head<<<BB, 256>>>(chroma, eps, w_mu, b_mu, w_var, b_var, out);
    k_hx0<<<BB, 256>>>(w_init, b_init);
    k_zpart<<<BB, 256>>>(w_ih_g);
    k_addz<<<dim3(TT, BB), 256>>>();
    k_dec_persist<<<128, 256, SMEM_BYTES>>>(w_hh_g, b_hh_g, w_hh_g2,
                                            b_ih_g2, b_hh_g2);
    k_logits<<<256, 256>>>(w_out, b_out, out);
}

// round 13
// speedup vs baseline: 5.2549x; 1.0717x over previous
#include <cuda_runtime.h>
#include <cuda_fp16.h>
#include <mma.h>
#include <cstdint>
#include <cstddef>
#include <math.h>

using namespace nvcuda;

#define BB 128
#define TT 256
#define RR 130
#define HH 1024
#define H3 3072
#define ZZ2 256
#define CC 24
#define ZC 280
#define KIN 410

// fp16 persistent-step shared memory layout (in halfs)
#define HLDH 136                  // sH row stride (128 + 8 pad)
#define WLDH 1040                 // resident W row stride (1024 + 16 pad)
#define CHK 128                   // K per chunk
#define NCH 8                     // chunks per 1024-K GEMM
#define OFF_SW 0                  // 48 x 1040 resident W
#define SW_H (48 * WLDH)          // 49920
#define OFF_SH SW_H               // triple-buffered A staging
#define SH_BUF (128 * HLDH)       // 17408 halfs per buffer
#define OFF_SWS (OFF_SH + 3 * SH_BUF)   // 102144: dec2 streamed-W staging (single buf)
#define SWS_BUF (48 * HLDH)       // 6528
#define OFF_SB (OFF_SWS + SWS_BUF)      // 108672 (halfs) -> float bias region
#define SMEMH (OFF_SB + 384)
#define SMEM_BYTES (SMEMH * 2)

static constexpr size_t GI_SZ = (size_t)TT * BB * H3;

__device__ __align__(128) float g_gi_f[GI_SZ];
__device__ __align__(128) float g_gi_b[GI_SZ];
__device__ __align__(128) float g_gi_gx[GI_SZ];
__device__ __align__(128) float g_h1all[(size_t)TT * BB * HH];
__device__ __align__(128) float g_zpart[BB * H3];
__device__ __align__(128) float g_zfull[BB * ZC];
__device__ __align__(128) float g_hf[2][BB * HH];
__device__ __align__(128) float g_hb[2][BB * HH];
__device__ __align__(128) float g_h0[2][BB * HH];
__device__ __align__(128) float g_h1[2][BB * HH];
// fp16 mirrors (MMA inputs)
__device__ __align__(128) __half g_hfh[2][BB * HH];
__device__ __align__(128) __half g_hbh[2][BB * HH];
__device__ __align__(128) __half g_h0h[2][BB * HH];
__device__ __align__(128) __half g_h1h[2][BB * HH];
__device__ __align__(128) __half g_wih2[(size_t)H3 * HH];   // w_ih_g2 in fp16

// software grid barriers (reset by k_init each invocation)
__device__ volatile int g_gen_ef; __device__ unsigned int g_cnt_ef;
__device__ volatile int g_gen_eb; __device__ unsigned int g_cnt_eb;
__device__ volatile int g_gen_1;  __device__ unsigned int g_cnt_1;
__device__ volatile int g_gen_2;  __device__ unsigned int g_cnt_2;

static constexpr size_t OFF_MU  = (size_t)BB * TT * RR;
static constexpr size_t OFF_STD = OFF_MU + (size_t)BB * ZZ2;
static constexpr size_t OFF_Z   = OFF_STD + (size_t)BB * ZZ2;

__device__ __forceinline__ float sigf(float v) { return 1.f / (1.f + expf(-v)); }
#define TF32(x) wmma::__float_to_tf32(x)

__device__ __forceinline__ float warp_sum(float v) {
#pragma unroll
    for (int off = 16; off > 0; off >>= 1)
        v += __shfl_xor_sync(0xffffffffu, v, off);
    return v;
}

// ---- cp.async helpers ------------------------------------------------------
__device__ __forceinline__ void cpa16(uint32_t dst, const void* src) {
    asm volatile("cp.async.cg.shared.global [%0], [%1], 16;" :: "r"(dst), "l"(src));
}
__device__ __forceinline__ void cpa_commit() { asm volatile("cp.async.commit_group;"); }
template <int N> __device__ __forceinline__ void cpa_wait() {
    asm volatile("cp.async.wait_group %0;" :: "n"(N));
}

// ---------------------------------------------------------------------------
__global__ void k_init() {
    int i = blockIdx.x * blockDim.x + threadIdx.x;
    if (i < BB * HH) {
        g_hf[0][i] = 0.f; g_hb[0][i] = 0.f;
        g_hfh[0][i] = __float2half_rn(0.f);
        g_hbh[0][i] = __float2half_rn(0.f);
    }
    if (i == 0) {
        g_gen_ef = 0; g_cnt_ef = 0;
        g_gen_eb = 0; g_cnt_eb = 0;
        g_gen_1 = 0;  g_cnt_1 = 0;
        g_gen_2 = 0;  g_cnt_2 = 0;
    }
}

// convert w_ih_g2 to fp16 once
__global__ void k_convw(const float* __restrict__ w) {
    size_t i = ((size_t)blockIdx.x * HH) + threadIdx.x * 4;
    float4 v = *(const float4*)(w + i);
    __half2 a = __floats2half2_rn(v.x, v.y);
    __half2 b = __floats2half2_rn(v.z, v.w);
    *(__half2*)(g_wih2 + i) = a;
    *(__half2*)(g_wih2 + i + 2) = b;
}

// generation barrier over nb co-resident blocks; target strictly increasing
__device__ __forceinline__ void group_barrier(unsigned int* cnt, volatile int* gen,
                                              int target, int nb) {
    __syncthreads();
    if (threadIdx.x == 0) {
        __threadfence();
        if (atomicAdd(cnt, 1u) == (unsigned)(nb - 1)) {
            atomicExch(cnt, 0u);
            __threadfence();
            *gen = target;
        } else {
            while (*gen < target) __nanosleep(32);
            __threadfence();
        }
    }
    __syncthreads();
}

__device__ __forceinline__ void wait_gen(volatile int* gen, int target) {
    if (threadIdx.x == 0) {
        while (*gen < target) __nanosleep(32);
        __threadfence();
    }
    __syncthreads();
}

// ---------------------------------------------------------------------------
// Input-side GEMMs for all timesteps: gi = A @ W^T + b_ih  (tf32, unchanged)
// ---------------------------------------------------------------------------
__global__ void __launch_bounds__(256) k_input_gemm(
    const float* __restrict__ x,
    const float* __restrict__ w_f, const float* __restrict__ bi_f,
    const float* __restrict__ w_b, const float* __restrict__ bi_b,
    const float* __restrict__ w_g, const float* __restrict__ bi_g)
{
    __shared__ __align__(16) float sm[8192];
    const int tid = threadIdx.x;
    const int warp = tid >> 5;
    const int wm = warp >> 1, wn = warp & 1;

    const int mode = blockIdx.z;
    const float* W  = (mode == 0) ? w_f : (mode == 1) ? w_b : w_g;
    const float* bi = (mode == 0) ? bi_f : (mode == 1) ? bi_b : bi_g;
    float* gout = (mode == 0) ? g_gi_f : (mode == 1) ? g_gi_b : g_gi_gx;
    const int wstride = (mode == 2) ? KIN : RR;

    const int m0 = blockIdx.y * 128;
    const int n0 = blockIdx.x * 64;
    float* sA = sm;
    float* sB = sm + 3072;

    wmma::fragment<wmma::accumulator, 16, 16, 8, float> c[2][2];
#pragma unroll
    for (int s = 0; s < 2; s++)
#pragma unroll
        for (int s2 = 0; s2 < 2; s2++) wmma::fill_fragment(c[s][s2], 0.f);

    for (int kt = 0; kt < 9; ++kt) {
        const int k0 = kt * 16;
#pragma unroll
        for (int i = 0; i < 8; i++) {
            int e = tid + i * 256;
            int r = e >> 4, kk = e & 15;
            int m = m0 + r, k = k0 + kk;
            int tstep = m >> 7, b = m & 127;
            float v = 0.f;
            if (k < RR) {
                if (mode < 2) v = x[(size_t)b * TT * RR + (size_t)tstep * RR + k];
                else if (tstep == 0) v = (k == RR - 1) ? 1.f : 0.f;
                else v = x[(size_t)b * TT * RR + (size_t)(tstep - 1) * RR + k];
            }
            sA[r * 24 + kk] = v;
        }
#pragma unroll
        for (int i = 0; i < 4; i++) {
            int e = tid + i * 256;
            int col = e >> 4, kk = e & 15;
            int n = n0 + col, k = k0 + kk;
            sB[col * 24 + kk] = (k < RR) ? W[(size_t)n * wstride + k] : 0.f;
        }
        __syncthreads();
#pragma unroll
        for (int ks = 0; ks < 2; ks++) {
            wmma::fragment<wmma::matrix_a, 16, 16, 8, wmma::precision::tf32, wmma::row_major> a[2];
            wmma::fragment<wmma::matrix_b, 16, 16, 8, wmma::precision::tf32, wmma::col_major> bf[2];
#pragma unroll
            for (int s = 0; s < 2; s++) {
                wmma::load_matrix_sync(a[s], sA + (wm * 32 + s * 16) * 24 + ks * 8, 24);
#pragma unroll
                for (int i = 0; i < a[s].num_elements; i++) a[s].x[i] = TF32(a[s].x[i]);
            }
#pragma unroll
            for (int s2 = 0; s2 < 2; s2++) {
                wmma::load_matrix_sync(bf[s2], sB + (wn * 32 + s2 * 16) * 24 + ks * 8, 24);
#pragma unroll
                for (int i = 0; i < bf[s2].num_elements; i++) bf[s2].x[i] = TF32(bf[s2].x[i]);
            }
#pragma unroll
            for (int s = 0; s < 2; s++)
#pragma unroll
                for (int s2 = 0; s2 < 2; s2++)
                    wmma::mma_sync(c[s][s2], a[s], bf[s2], c[s][s2]);
        }
        __syncthreads();
    }
#pragma unroll
    for (int s = 0; s < 2; s++)
#pragma unroll
        for (int s2 = 0; s2 < 2; s2++)
            wmma::store_matrix_sync(sm + (wm * 32 + s * 16) * 64 + (wn * 32 + s2 * 16),
                                    c[s][s2], 64, wmma::mem_row_major);
    __syncthreads();
#pragma unroll
    for (int i = 0; i < 8; i++) {
        int e = tid + i * 256;
        int r = e >> 4, c4 = (e & 15) << 2;
        int n = n0 + c4;
        float4 v = *(float4*)(sm + r * 64 + c4);
        v.x += bi[n]; v.y += bi[n + 1]; v.z += bi[n + 2]; v.w += bi[n + 3];
        *(float4*)(gout + (size_t)(m0 + r) * H3 + n) = v;
    }
}

// ---------------------------------------------------------------------------
// Load a 48-row W slice into resident SMEM as fp16, [col][k], ld WLDH.
// ---------------------------------------------------------------------------
__device__ __forceinline__ void load_w_res_h(const float* __restrict__ W,
                                             __half* __restrict__ sW, int ctile) {
    const int tid = threadIdx.x;
#pragma unroll 4
    for (int i = 0; i < 48; i++) {
        int e = tid + (i << 8);
        int col = e >> 8, k4 = (e & 255) << 2;
        int q = col >> 4, jl = col & 15;
        float4 v = *(const float4*)(W + (size_t)(q * HH + ctile * 16 + jl) * HH + k4);
        __half2 a = __floats2half2_rn(v.x, v.y);
        __half2 b = __floats2half2_rn(v.z, v.w);
        *(__half2*)(sW + col * WLDH + k4) = a;
        *(__half2*)(sW + col * WLDH + k4 + 2) = b;
    }
}

// stage one 128x128 fp16 A chunk via cp.async (8 x 16B per thread)
__device__ __forceinline__ void stage_h(uint32_t sh_addr, const __half* __restrict__ hsrc, int c) {
    const int tid = threadIdx.x;
#pragma unroll
    for (int i = 0; i < 8; i++) {
        int u = tid + (i << 8);        // 0..2047 16B-units
        int row = u >> 4, un = u & 15;
        cpa16(sh_addr + (uint32_t)(row * HLDH + un * 8) * 2,
              hsrc + (size_t)row * HH + c * CHK + un * 8);
    }
}

// stage one 48x128 fp16 streamed-W chunk via cp.async (rows = gate cols)
__device__ __forceinline__ void stage_w(uint32_t sw_addr, const __half* __restrict__ wsrc,
                                        int ctile, int c) {
    const int tid = threadIdx.x;
#pragma unroll
    for (int i = 0; i < 3; i++) {
        int u = tid + (i << 8);
        if (u < 768) {
            int col = u >> 4, un = u & 15;
            int g = (col >> 4) * HH + ctile * 16 + (col & 15);
            cpa16(sw_addr + (uint32_t)(col * HLDH + un * 8) * 2,
                  wsrc + (size_t)g * HH + c * CHK + un * 8);
        }
    }
}

// ---- split-K2 MMA chunks: warp = (mgrp 0..3) x (khalf 0..1) ---------------
// Each warp: rows [mgrp*32, +32), ks in [khalf*4, khalf*4+4) of the 8 ks.
__device__ __forceinline__ void mma_chunk_res2(
    wmma::fragment<wmma::accumulator, 16, 16, 16, float> (*acc)[3],
    const __half* __restrict__ sH, const __half* __restrict__ sW,
    int c, int mgrp, int khalf)
{
#pragma unroll
    for (int kss = 0; kss < 4; kss++) {
        const int ks = khalf * 4 + kss;
        wmma::fragment<wmma::matrix_a, 16, 16, 16, __half, wmma::row_major> a[2];
#pragma unroll
        for (int mt = 0; mt < 2; mt++)
            wmma::load_matrix_sync(a[mt], sH + (mgrp * 32 + mt * 16) * HLDH + ks * 16, HLDH);
#pragma unroll
        for (int q = 0; q < 3; q++) {
            wmma::fragment<wmma::matrix_b, 16, 16, 16, __half, wmma::col_major> b;
            wmma::load_matrix_sync(b, sW + (q * 16) * WLDH + c * CHK + ks * 16, WLDH);
#pragma unroll
            for (int mt = 0; mt < 2; mt++)
                wmma::mma_sync(acc[mt][q], a[mt], b, acc[mt][q]);
        }
    }
}

__device__ __forceinline__ void mma_chunk_str2(
    wmma::fragment<wmma::accumulator, 16, 16, 16, float> (*acc)[3],
    const __half* __restrict__ sH, const __half* __restrict__ sWs,
    int mgrp, int khalf)
{
#pragma unroll
    for (int kss = 0; kss < 4; kss++) {
        const int ks = khalf * 4 + kss;
        wmma::fragment<wmma::matrix_a, 16, 16, 16, __half, wmma::row_major> a[2];
#pragma unroll
        for (int mt = 0; mt < 2; mt++)
            wmma::load_matrix_sync(a[mt], sH + (mgrp * 32 + mt * 16) * HLDH + ks * 16, HLDH);
#pragma unroll
        for (int q = 0; q < 3; q++) {
            wmma::fragment<wmma::matrix_b, 16, 16, 16, __half, wmma::col_major> b;
            wmma::load_matrix_sync(b, sWs + (q * 16) * HLDH + ks * 16, HLDH);
#pragma unroll
            for (int mt = 0; mt < 2; mt++)
                wmma::mma_sync(acc[mt][q], a[mt], b, acc[mt][q]);
        }
    }
}

// ---------------------------------------------------------------------------
// GRU step (fp16, splitK2, triple-buffered single-sync chunk loop)
// ---------------------------------------------------------------------------
__device__ __forceinline__ void gru_step_f16(
    const float* __restrict__ h_old, const __half* __restrict__ h_oldh,
    float* __restrict__ h_new, __half* __restrict__ h_newh,
    const __half* __restrict__ sW, const float* __restrict__ sB,
    const float* __restrict__ gi1, int ctile,
    __half* __restrict__ sH, uint32_t sH_addr)
{
    const int tid = threadIdx.x, warp = tid >> 5;
    const int mgrp = warp & 3, khalf = warp >> 2;

    // epilogue operand prefetch (latency hidden under the GEMM)
    float pgi[24], pho[8];
#pragma unroll
    for (int i = 0; i < 8; i++) {
        int e = tid + (i << 8);
        int row = e >> 4, jl = e & 15, j = ctile * 16 + jl;
        const float* gr = gi1 + (size_t)row * H3 + j;
        pgi[i * 3 + 0] = __ldg(gr);
        pgi[i * 3 + 1] = __ldg(gr + HH);
        pgi[i * 3 + 2] = __ldg(gr + 2 * HH);
        pho[i] = __ldcg(h_old + (size_t)row * HH + j);
    }

    wmma::fragment<wmma::accumulator, 16, 16, 16, float> acc[2][3];
#pragma unroll
    for (int mt = 0; mt < 2; mt++)
#pragma unroll
        for (int q = 0; q < 3; q++) wmma::fill_fragment(acc[mt][q], 0.f);

    stage_h(sH_addr, h_oldh, 0);               cpa_commit();
    stage_h(sH_addr + SH_BUF * 2, h_oldh, 1);  cpa_commit();
    for (int c = 0; c < NCH; c++) {
        if (c < NCH - 1) cpa_wait<1>(); else cpa_wait<0>();
        __syncthreads();
        if (c + 2 < NCH) {
            stage_h(sH_addr + (uint32_t)((c + 2) % 3) * SH_BUF * 2, h_oldh, c + 2);
            cpa_commit();
        }
        mma_chunk_res2(acc, sH + (c % 3) * SH_BUF, sW, c, mgrp, khalf);
    }
    __syncthreads();

    // split-K reduce (2 rounds through sG) + gates
    float* sG = (float*)sH;   // 128 x 48 fp32
    if (khalf == 0)
#pragma unroll
        for (int mt = 0; mt < 2; mt++)
#pragma unroll
            for (int q = 0; q < 3; q++)
                wmma::store_matrix_sync(sG + (mgrp * 32 + mt * 16) * 48 + q * 16,
                                        acc[mt][q], 48, wmma::mem_row_major);
    __syncthreads();
    float vh[24];
#pragma unroll
    for (int i = 0; i < 8; i++) {
        int e = tid + (i << 8);
        int row = e >> 4, jl = e & 15;
        vh[i * 3 + 0] = sG[row * 48 + jl];
        vh[i * 3 + 1] = sG[row * 48 + 16 + jl];
        vh[i * 3 + 2] = sG[row * 48 + 32 + jl];
    }
    __syncthreads();
    if (khalf == 1)
#pragma unroll
        for (int mt = 0; mt < 2; mt++)
#pragma unroll
            for (int q = 0; q < 3; q++)
                wmma::store_matrix_sync(sG + (mgrp * 32 + mt * 16) * 48 + q * 16,
                                        acc[mt][q], 48, wmma::mem_row_major);
    __syncthreads();
#pragma unroll
    for (int i = 0; i < 8; i++) {
        int e = tid + (i << 8);
        int row = e >> 4, jl = e & 15;
        int j = ctile * 16 + jl;
        float hr = vh[i * 3 + 0] + sG[row * 48 + jl]      + sB[jl];
        float hz = vh[i * 3 + 1] + sG[row * 48 + 16 + jl] + sB[16 + jl];
        float hn = vh[i * 3 + 2] + sG[row * 48 + 32 + jl] + sB[32 + jl];
        float r = sigf(pgi[i * 3 + 0] + hr);
        float u = sigf(pgi[i * 3 + 1] + hz);
        float n = tanhf(pgi[i * 3 + 2] + r * hn);
        float o = (1.f - u) * n + u * pho[i];
        h_new[(size_t)row * HH + j] = o;
        h_newh[(size_t)row * HH + j] = __float2half_rn(o);
    }
    // no trailing sync: group_barrier / wait_gen leads with __syncthreads
}

// ---------------------------------------------------------------------------
// Persistent encoder: 64 blocks/direction, per-direction barriers.
// ---------------------------------------------------------------------------
__global__ void __launch_bounds__(256) k_enc_persist(
    const float* __restrict__ w_hh_f, const float* __restrict__ b_hh_f,
    const float* __restrict__ w_hh_b, const float* __restrict__ b_hh_b)
{
    extern __shared__ __align__(16) __half smh[];
    __half* sW = smh + OFF_SW;
    __half* sH = smh + OFF_SH;
    float* sB = (float*)(smh + OFF_SB);
    uint32_t sH_addr = (uint32_t)__cvta_generic_to_shared(sH);
    const int tid = threadIdx.x;
    const int dir = blockIdx.x >> 6, ctile = blockIdx.x & 63;
    const float* W   = dir ? w_hh_b : w_hh_f;
    const float* bhh = dir ? b_hh_b : b_hh_f;
    unsigned int* cnt = dir ? &g_cnt_eb : &g_cnt_ef;
    volatile int* gen = dir ? &g_gen_eb : &g_gen_ef;

    load_w_res_h(W, sW, ctile);
    if (tid < 48) {
        int q = tid >> 4, jl = tid & 15;
        sB[tid] = bhh[q * HH + ctile * 16 + jl];
    }
    __syncthreads();

    for (int t = 0; t < TT; t++) {
        const int p = t & 1;
        const float* h_old  = dir ? g_hb[p] : g_hf[p];
        const __half* h_oldh = dir ? g_hbh[p] : g_hfh[p];
        float* h_new  = dir ? g_hb[1 - p] : g_hf[1 - p];
        __half* h_newh = dir ? g_hbh[1 - p] : g_hfh[1 - p];
        const float* gi = dir ? g_gi_b + (size_t)(TT - 1 - t) * BB * H3
                              : g_gi_f + (size_t)t * BB * H3;
        gru_step_f16(h_old, h_oldh, h_new, h_newh, sW, sB, gi, ctile, sH, sH_addr);
        group_barrier(cnt, gen, t + 1, 64);
    }
}

// ---------------------------------------------------------------------------
// Decoder cell2 step: interleaved 16-chunk loop (even = Wi*h0n streamed,
// odd = Wh*h1p resident), splitK2, single-buffer sWs, 2-round dual reduce.
// ---------------------------------------------------------------------------
__device__ __forceinline__ void dec2_step_f16(
    const float* __restrict__ h1p, const __half* __restrict__ h0nh,
    const __half* __restrict__ h1ph,
    float* __restrict__ h1n, __half* __restrict__ h1nh,
    const __half* __restrict__ sWh, const float* __restrict__ sB,
    int ctile, __half* __restrict__ sH, uint32_t sH_addr,
    __half* __restrict__ sWs, uint32_t sWs_addr, int t)
{
    const int tid = threadIdx.x, warp = tid >> 5;
    const int mgrp = warp & 3, khalf = warp >> 2;

    float pho[8];
#pragma unroll
    for (int i = 0; i < 8; i++) {
        int e = tid + (i << 8);
        int row = e >> 4, jl = e & 15;
        pho[i] = __ldcg(h1p + (size_t)row * HH + ctile * 16 + jl);
    }

    wmma::fragment<wmma::accumulator, 16, 16, 16, float> ai[2][3], ah[2][3];
#pragma unroll
    for (int mt = 0; mt < 2; mt++)
#pragma unroll
        for (int q = 0; q < 3; q++) { wmma::fill_fragment(ai[mt][q], 0.f); wmma::fill_fragment(ah[mt][q], 0.f); }

    // pre-stage: group {A(iter0)=h0n c0, W0}, group {A(iter1)=h1p c0}
    stage_h(sH_addr, h0nh, 0);
    stage_w(sWs_addr, g_wih2, ctile, 0);
    cpa_commit();
    stage_h(sH_addr + SH_BUF * 2, h1ph, 0);
    cpa_commit();

    for (int v = 0; v < 16; v++) {
        if ((v & 1) && v < 15) cpa_wait<1>(); else cpa_wait<0>();
        __syncthreads();
        if (v + 2 < 16) {
            const int nv = v + 2;
            stage_h(sH_addr + (uint32_t)(nv % 3) * SH_BUF * 2,
                    (nv & 1) ? h1ph : h0nh, nv >> 1);
            if (v & 1) stage_w(sWs_addr, g_wih2, ctile, (v + 1) >> 1);
            cpa_commit();
        }
        if (v & 1) mma_chunk_res2(ah, sH + (v % 3) * SH_BUF, sWh, v >> 1, mgrp, khalf);
        else       mma_chunk_str2(ai, sH + (v % 3) * SH_BUF, sWs, mgrp, khalf);
    }
    __syncthreads();

    // 2-round dual-matrix split-K reduce
    float* sG0 = (float*)sH;          // 128 x 48
    float* sG1 = sG0 + 6144;          // 128 x 48
    if (khalf == 0)
#pragma unroll
        for (int mt = 0; mt < 2; mt++)
#pragma unroll
            for (int q = 0; q < 3; q++) {
                wmma::store_matrix_sync(sG0 + (mgrp * 32 + mt * 16) * 48 + q * 16,
                                        ai[mt][q], 48, wmma::mem_row_major);
                wmma::store_matrix_sync(sG1 + (mgrp * 32 + mt * 16) * 48 + q * 16,
                                        ah[mt][q], 48, wmma::mem_row_major);
            }
    __syncthreads();
    float vvi[24], vvh[24];
#pragma unroll
    for (int i = 0; i < 8; i++) {
        int e = tid + (i << 8); int row = e >> 4, jl = e & 15;
        vvi[i * 3 + 0] = sG0[row * 48 + jl];
        vvi[i * 3 + 1] = sG0[row * 48 + 16 + jl];
        vvi[i * 3 + 2] = sG0[row * 48 + 32 + jl];
        vvh[i * 3 + 0] = sG1[row * 48 + jl];
        vvh[i * 3 + 1] = sG1[row * 48 + 16 + jl];
        vvh[i * 3 + 2] = sG1[row * 48 + 32 + jl];
    }
    __syncthreads();
    if (khalf == 1)
#pragma unroll
        for (int mt = 0; mt < 2; mt++)
#pragma unroll
            for (int q = 0; q < 3; q++) {
                wmma::store_matrix_sync(sG0 + (mgrp * 32 + mt * 16) * 48 + q * 16,
                                        ai[mt][q], 48, wmma::mem_row_major);
                wmma::store_matrix_sync(sG1 + (mgrp * 32 + mt * 16) * 48 + q * 16,
                                        ah[mt][q], 48, wmma::mem_row_major);
            }
    __syncthreads();
#pragma unroll
    for (int i = 0; i < 8; i++) {
        int e = tid + (i << 8);
        int row = e >> 4, jl = e & 15;
        int j = ctile * 16 + jl;
        float ir  = vvi[i * 3 + 0] + sG0[row * 48 + jl]      + sB[jl];
        float iz  = vvi[i * 3 + 1] + sG0[row * 48 + 16 + jl] + sB[16 + jl];
        float in_ = vvi[i * 3 + 2] + sG0[row * 48 + 32 + jl] + sB[32 + jl];
        float hr = vvh[i * 3 + 0] + sG1[row * 48 + jl]      + sB[48 + jl];
        float hz = vvh[i * 3 + 1] + sG1[row * 48 + 16 + jl] + sB[64 + jl];
        float hn = vvh[i * 3 + 2] + sG1[row * 48 + 32 + jl] + sB[80 + jl];
        float r = sigf(ir + hr);
        float u = sigf(iz + hz);
        float n = tanhf(in_ + r * hn);
        float o = (1.f - u) * n + u * pho[i];
        h1n[(size_t)row * HH + j] = o;
        h1nh[(size_t)row * HH + j] = __float2half_rn(o);
        g_h1all[((size_t)t * BB + row) * HH + j] = o;
    }
}

// ---------------------------------------------------------------------------
// Persistent decoder: blocks 0..63 = cell1 chain, 64..127 = cell2 chain.
// ---------------------------------------------------------------------------
__global__ void __launch_bounds__(256) k_dec_persist(
    const float* __restrict__ w_hh_g,  const float* __restrict__ b_hh_g,
    const float* __restrict__ w_hh_g2,
    const float* __restrict__ b_ih_g2, const float* __restrict__ b_hh_g2)
{
    extern __shared__ __align__(16) __half smh[];
    __half* sW = smh + OFF_SW;
    __half* sH = smh + OFF_SH;
    __half* sWs = smh + OFF_SWS;
    float* sB = (float*)(smh + OFF_SB);
    uint32_t sH_addr = (uint32_t)__cvta_generic_to_shared(sH);
    uint32_t sWs_addr = (uint32_t)__cvta_generic_to_shared(sWs);
    const int tid = threadIdx.x;

    if (blockIdx.x < 64) {
        const int ctile = blockIdx.x;
        load_w_res_h(w_hh_g, sW, ctile);
        if (tid < 48) {
            int q = tid >> 4, jl = tid & 15;
            sB[tid] = b_hh_g[q * HH + ctile * 16 + jl];
        }
        __syncthreads();
        for (int t = 0; t < TT; t++) {
            if (t >= 2) wait_gen(&g_gen_2, t - 1);   // buffer reuse vs cell2 readers
            const int p = t & 1;
            gru_step_f16(g_h0[p], g_h0h[p], g_h0[1 - p], g_h0h[1 - p], sW, sB,
                         g_gi_gx + (size_t)t * BB * H3, ctile, sH, sH_addr);
            group_barrier(&g_cnt_1, &g_gen_1, t + 1, 64);
        }
    } else {
        const int ctile = blockIdx.x - 64;
        load_w_res_h(w_hh_g2, sW, ctile);
        if (tid < 48) {
            int q = tid >> 4, jl = tid & 15;
            sB[tid]      = b_ih_g2[q * HH + ctile * 16 + jl];
            sB[48 + tid] = b_hh_g2[q * HH + ctile * 16 + jl];
        }
        __syncthreads();
        for (int t = 0; t < TT; t++) {
            wait_gen(&g_gen_1, t + 1);               // h0n(t) ready
            const int p = t & 1;
            const float* h1p  = (t == 0) ? g_h0[1] : g_h1[p];
            const __half* h1ph = (t == 0) ? g_h0h[1] : g_h1h[p];
            dec2_step_f16(h1p, g_h0h[1 - p], h1ph, g_h1[1 - p], g_h1h[1 - p],
                          sW, sB, ctile, sH, sH_addr, sWs, sWs_addr, t);
            group_barrier(&g_cnt_2, &g_gen_2, t + 1, 64);
        }
    }
}

// ---------------------------------------------------------------------------
// mu / std / z heads — warp-dot, coalesced weight reads.
// ---------------------------------------------------------------------------
__global__ void __launch_bounds__(256) k_head(
    const float* __restrict__ chroma, const float* __restrict__ eps,
    const float* __restrict__ w_mu, const float* __restrict__ b_mu,
    const float* __restrict__ w_var, const float* __restrict__ b_var,
    float* __restrict__ out)
{
    __shared__ float sh[2048];
    __shared__ float sacc[2 * ZZ2];
    int b = blockIdx.x, tid = threadIdx.x;
    int warp = tid >> 5, lane = tid & 31;
    for (int i = tid; i < HH; i += 256) {
        sh[i] = g_hf[0][(size_t)b * HH + i];
        sh[HH + i] = g_hb[0][(size_t)b * HH + i];
    }
    __syncthreads();
    for (int task = warp; task < 2 * ZZ2; task += 8) {
        int head = task >> 8, j = task & 255;
        const float* w = (head ? w_var : w_mu) + (size_t)j * 2048;
        float acc = 0.f;
        for (int k = lane; k < 2048; k += 32) acc += sh[k] * __ldg(w + k);
        acc = warp_sum(acc);
        if (lane == 0) sacc[task] = acc + (head ? b_var[j] : b_mu[j]);
    }
    __syncthreads();
    if (tid < ZZ2) {
        int j = tid;
        float accm = sacc[j];
        float std = expf(sacc[ZZ2 + j]);
        float z = accm + std * eps[(size_t)b * ZZ2 + j];
        g_zfull[b * ZC + j] = z;
        out[OFF_MU + (size_t)b * ZZ2 + j] = accm;
        out[OFF_STD + (size_t)b * ZZ2 + j] = std;
        out[OFF_Z + (size_t)b * ZC + j] = z;
        if (j < CC) {
            float cv = chroma[b * CC + j];
            g_zfull[b * ZC + ZZ2 + j] = cv;
            out[OFF_Z + (size_t)b * ZC + ZZ2 + j] = cv;
        }
    }
}

__global__ void __launch_bounds__(256) k_hx0(
    const float* __restrict__ w_init, const float* __restrict__ b_init)
{
    __shared__ float sz[ZC];
    int b = blockIdx.x, tid = threadIdx.x;
    int warp = tid >> 5, lane = tid & 31;
    for (int i = tid; i < ZC; i += 256) sz[i] = g_zfull[b * ZC + i];
    __syncthreads();
    for (int j = warp; j < HH; j += 8) {
        const float* w = w_init + (size_t)j * ZC;
        float acc = 0.f;
        for (int k = lane; k < ZC; k += 32) acc += sz[k] * __ldg(w + k);
        acc = warp_sum(acc);
        if (lane == 0) {
            float v = acc + b_init[j];
            g_h0[0][(size_t)b * HH + j] = v;
            g_h0h[0][(size_t)b * HH + j] = __float2half_rn(v);
        }
    }
}

__global__ void __launch_bounds__(256) k_zpart(const float* __restrict__ w_ih_g)
{
    __shared__ float sz[ZC];
    int b = blockIdx.x, tid = threadIdx.x;
    int warp = tid >> 5, lane = tid & 31;
    for (int i = tid; i < ZC; i += 256) sz[i] = g_zfull[b * ZC + i];
    __syncthreads();
    for (int j = warp; j < H3; j += 8) {
        const float* w = w_ih_g + (size_t)j * KIN + RR;
        float acc = 0.f;
        for (int k = lane; k < ZC; k += 32) acc += sz[k] * __ldg(w + k);
        acc = warp_sum(acc);
        if (lane == 0) g_zpart[(size_t)b * H3 + j] = acc;
    }
}

// Fold zpart into gi_gx so dec1 reads a single preactivation stream.
__global__ void __launch_bounds__(256) k_addz() {
    int t = blockIdx.x, b = blockIdx.y, tid = threadIdx.x;
    float4* dst = (float4*)(g_gi_gx + ((size_t)t * BB + b) * H3);
    const float4* src = (const float4*)(g_zpart + (size_t)b * H3);
#pragma unroll
    for (int i = 0; i < 3; i++) {
        int e = tid + i * 256;
        float4 d = dst[e], s = src[e];
        d.x += s.x; d.y += s.y; d.z += s.z; d.w += s.w;
        dst[e] = d;
    }
}

// ---------------------------------------------------------------------------
// Final logits + log_softmax (tf32, unchanged)
// ---------------------------------------------------------------------------
__global__ void __launch_bounds__(256) k_logits(
    const float* __restrict__ w_out, const float* __restrict__ b_out,
    float* __restrict__ out)
{
    __shared__ __align__(16) float sm[10880];
    const int tid = threadIdx.x, warp = tid >> 5, lane = tid & 31;
    const int m0 = blockIdx.x * 128;
    float* sH = sm;
    float* sW = sm + 5120;

    wmma::fragment<wmma::accumulator, 16, 16, 8, float> c[9];
#pragma unroll
    for (int q = 0; q < 9; q++) wmma::fill_fragment(c[q], 0.f);

    for (int kt = 0; kt < 32; ++kt) {
        const int k0 = kt * 32;
#pragma unroll
        for (int i = 0; i < 4; i++) {
            int e = tid + i * 256;
            int row = e >> 3, kk = (e & 7) << 2;
            *(float4*)(sH + row * 40 + kk) =
                *(const float4*)(g_h1all + (size_t)(m0 + row) * HH + k0 + kk);
        }
#pragma unroll
        for (int i = 0; i < 5; i++) {
            int e = tid + i * 256;
            if (e < 1152) {
                int col = e >> 3, kk = (e & 7) << 2;
                float4 v = make_float4(0.f, 0.f, 0.f, 0.f);
                if (col < RR) v = *(const float4*)(w_out + (size_t)col * HH + k0 + kk);
                *(float4*)(sW + col * 40 + kk) = v;
            }
        }
        __syncthreads();
#pragma unroll
        for (int ks = 0; ks < 4; ks++) {
            wmma::fragment<wmma::matrix_a, 16, 16, 8, wmma::precision::tf32, wmma::row_major> a;
            wmma::load_matrix_sync(a, sH + warp * 16 * 40 + ks * 8, 40);
#pragma unroll
            for (int i = 0; i < a.num_elements; i++) a.x[i] = TF32(a.x[i]);
#pragma unroll
            for (int q = 0; q < 9; q++) {
                wmma::fragment<wmma::matrix_b, 16, 16, 8, wmma::precision::tf32, wmma::col_major> bf;
                wmma::load_matrix_sync(bf, sW + q * 16 * 40 + ks * 8, 40);
#pragma unroll
                for (int i = 0; i < bf.num_elements; i++) bf.x[i] = TF32(bf.x[i]);
                wmma::mma_sync(c[q], a, bf, c[q]);
            }
        }
        __syncthreads();
    }
    float* sG = sm;
    for (int half = 0; half < 2; half++) {
        __syncthreads();
        if ((warp >> 2) == half) {
#pragma unroll
            for (int q = 0; q < 9; q++)
                wmma::store_matrix_sync(sG + (warp & 3) * 16 * 144 + q * 16, c[q], 144,
                                        wmma::mem_row_major);
        }
        __syncthreads();
        for (int rr = warp; rr < 64; rr += 8) {
            int m = m0 + half * 64 + rr;
            float mx = -1e30f;
            for (int j = lane; j < RR; j += 32) {
                float v = sG[rr * 144 + j] + b_out[j];
                mx = fmaxf(mx, v);
            }
#pragma unroll
            for (int off = 16; off > 0; off >>= 1)
                mx = fmaxf(mx, __shfl_xor_sync(0xffffffffu, mx, off));
            float s = 0.f;
            for (int j = lane; j < RR; j += 32)
                s += expf(sG[rr * 144 + j] + b_out[j] - mx);
#pragma unroll
            for (int off = 16; off > 0; off >>= 1)
                s += __shfl_xor_sync(0xffffffffu, s, off);
            float lse = mx + logf(s);
            int b = m & 127, t = m >> 7;
            float* orow = out + ((size_t)b * TT + t) * RR;
            for (int j = lane; j < RR; j += 32)
                orow[j] = sG[rr * 144 + j] + b_out[j] - lse;
        }
    }
}

// ---------------------------------------------------------------------------
extern "C" void kernel_launch(void* const* d_in, const int* in_sizes, int n_in,
                              void* d_out, int out_size) {
    (void)in_sizes; (void)n_in; (void)out_size;
    const float* x       = (const float*)d_in[0];
    const float* chroma  = (const float*)d_in[1];
    const float* eps     = (const float*)d_in[2];
    const float* w_ih_f  = (const float*)d_in[3];
    const float* w_hh_f  = (const float*)d_in[4];
    const float* b_ih_f  = (const float*)d_in[5];
    const float* b_hh_f  = (const float*)d_in[6];
    const float* w_ih_b  = (const float*)d_in[7];
    const float* w_hh_b  = (const float*)d_in[8];
    const float* b_ih_b  = (const float*)d_in[9];
    const float* b_hh_b  = (const float*)d_in[10];
    const float* w_mu    = (const float*)d_in[11];
    const float* b_mu    = (const float*)d_in[12];
    const float* w_var   = (const float*)d_in[13];
    const float* b_var   = (const float*)d_in[14];
    const float* w_init  = (const float*)d_in[15];
    const float* b_init  = (const float*)d_in[16];
    const float* w_ih_g  = (const float*)d_in[17];
    const float* w_hh_g  = (const float*)d_in[18];
    const float* b_ih_g  = (const float*)d_in[19];
    const float* b_hh_g  = (const float*)d_in[20];
    const float* w_ih_g2 = (const float*)d_in[21];
    const float* w_hh_g2 = (const float*)d_in[22];
    const float* b_ih_g2 = (const float*)d_in[23];
    const float* b_hh_g2 = (const float*)d_in[24];
    const float* w_out   = (const float*)d_in[25];
    const float* b_out   = (const float*)d_in[26];
    float* out = (float*)d_out;

    cudaFuncSetAttribute(k_enc_persist, cudaFuncAttributeMaxDynamicSharedMemorySize, SMEM_BYTES);
    cudaFuncSetAttribute(k_dec_persist, cudaFuncAttributeMaxDynamicSharedMemorySize, SMEM_BYTES);

    k_init<<<512, 256>>>();
    k_convw<<<H3, 256>>>(w_ih_g2);
    k_input_gemm<<<dim3(48, 256, 3), 256>>>(x, w_ih_f, b_ih_f, w_ih_b, b_ih_b,
                                            w_ih_g, b_ih_g);
    k_enc_persist<<<128, 256, SMEM_BYTES>>>(w_hh_f, b_hh_f, w_hh_b, b_hh_b);
    k_head<<<BB, 256>>>(chroma, eps, w_mu, b_mu, w_var, b_var, out);
    k_hx0<<<BB, 256>>>(w_init, b_init);
    k_zpart<<<BB, 256>>>(w_ih_g);
    k_addz<<<dim3(TT, BB), 256>>>();
    k_dec_persist<<<128, 256, SMEM_BYTES>>>(w_hh_g, b_hh_g, w_hh_g2,
                                            b_ih_g2, b_hh_g2);
    k_logits<<<256, 256>>>(w_out, b_out, out);
}